// round 1
// baseline (speedup 1.0000x reference)
#include <cuda_runtime.h>
#include <cuda_bf16.h>
#include <cstdint>

// ---------------------------------------------------------------------------
// Problem constants
// ---------------------------------------------------------------------------
#define B_SZ     2
#define L_SEQ    2048
#define D_MODEL  2048
#define N_HEADS  16
#define D_HEAD   128
#define HEAD_V   256
#define KEY_DIM  2048
#define VALUE_DIM 4096
#define TOTAL_PROJ 12320           // 2*2048 + 2*4096 + 2*16
#define CONV_CH  8192              // 2*KEY_DIM + VALUE_DIM
#define BL       (B_SZ * L_SEQ)    // 4096

// ---------------------------------------------------------------------------
// Scratch (static device globals; no allocation allowed)
// ---------------------------------------------------------------------------
__device__ float g_proj[(size_t)BL * TOTAL_PROJ];   // 4096 x 12320  (~202 MB)
__device__ float g_y[(size_t)BL * CONV_CH];         // 4096 x 8192   (~134 MB)
__device__ float g_eg[BL * N_HEADS];                // exp(g) per (b,l,h)
__device__ float g_beta[BL * N_HEADS];              // sigmoid(b)

// ---------------------------------------------------------------------------
// Kernel 1: SGEMM  proj = X[4096,2048] @ W[2048,12320]   (fp32)
// 128x128 block tile, BK=8, 8x8 per thread, 256 threads.
// ---------------------------------------------------------------------------
__global__ __launch_bounds__(256) void sgemm_kernel(
    const float* __restrict__ A,     // [4096, 2048]
    const float* __restrict__ Bm)    // [2048, 12320]
{
    const int M = BL, N = TOTAL_PROJ, K = D_MODEL;
    __shared__ float As[8][128];
    __shared__ float Bs[8][128];

    const int bx = blockIdx.x;      // N tile (0..96)
    const int by = blockIdx.y;      // M tile (0..31)
    const int tid = threadIdx.x;
    const int tx = tid & 15;        // 0..15
    const int ty = tid >> 4;        // 0..15

    // A load: one float4 per thread: row = tid/2, kcol = (tid&1)*4
    const int aRow = tid >> 1;
    const int aCol = (tid & 1) << 2;
    // B load: one float4 per thread: krow = tid/32, col = (tid&31)*4
    const int bRow = tid >> 5;
    const int bCol = (tid & 31) << 2;

    const float* Ab = A + (size_t)(by * 128) * K;
    const int colBase = bx * 128;

    float acc[8][8];
#pragma unroll
    for (int i = 0; i < 8; i++)
#pragma unroll
        for (int j = 0; j < 8; j++) acc[i][j] = 0.f;

    for (int k0 = 0; k0 < K; k0 += 8) {
        // load A tile
        float4 av = *(const float4*)(Ab + (size_t)aRow * K + k0 + aCol);
        // load B tile (guard last N tile)
        float4 bv;
        const int gcol = colBase + bCol;
        const float* Brow = Bm + (size_t)(k0 + bRow) * N;
        if (gcol + 3 < N) {
            bv = *(const float4*)(Brow + gcol);
        } else {
            bv.x = (gcol + 0 < N) ? Brow[gcol + 0] : 0.f;
            bv.y = (gcol + 1 < N) ? Brow[gcol + 1] : 0.f;
            bv.z = (gcol + 2 < N) ? Brow[gcol + 2] : 0.f;
            bv.w = (gcol + 3 < N) ? Brow[gcol + 3] : 0.f;
        }
        As[aCol + 0][aRow] = av.x;
        As[aCol + 1][aRow] = av.y;
        As[aCol + 2][aRow] = av.z;
        As[aCol + 3][aRow] = av.w;
        *(float4*)&Bs[bRow][bCol] = bv;
        __syncthreads();

#pragma unroll
        for (int kk = 0; kk < 8; kk++) {
            float ar[8], br[8];
            float4 a0 = *(const float4*)&As[kk][ty * 8];
            float4 a1 = *(const float4*)&As[kk][ty * 8 + 4];
            float4 b0 = *(const float4*)&Bs[kk][tx * 8];
            float4 b1 = *(const float4*)&Bs[kk][tx * 8 + 4];
            ar[0]=a0.x; ar[1]=a0.y; ar[2]=a0.z; ar[3]=a0.w;
            ar[4]=a1.x; ar[5]=a1.y; ar[6]=a1.z; ar[7]=a1.w;
            br[0]=b0.x; br[1]=b0.y; br[2]=b0.z; br[3]=b0.w;
            br[4]=b1.x; br[5]=b1.y; br[6]=b1.z; br[7]=b1.w;
#pragma unroll
            for (int i = 0; i < 8; i++)
#pragma unroll
                for (int j = 0; j < 8; j++) acc[i][j] += ar[i] * br[j];
        }
        __syncthreads();
    }

    // store
#pragma unroll
    for (int i = 0; i < 8; i++) {
        const int row = by * 128 + ty * 8 + i;
        float* Crow = g_proj + (size_t)row * N;
#pragma unroll
        for (int j = 0; j < 8; j += 4) {
            const int col = colBase + tx * 8 + j;
            if (col + 3 < N) {
                *(float4*)(Crow + col) =
                    make_float4(acc[i][j], acc[i][j+1], acc[i][j+2], acc[i][j+3]);
            } else {
#pragma unroll
                for (int jj = 0; jj < 4; jj++)
                    if (col + jj < N) Crow[col + jj] = acc[i][j + jj];
            }
        }
    }
}

// ---------------------------------------------------------------------------
// Kernel 2: per-(b,l,h) scalars:  eg = exp(g),  beta = sigmoid(b)
// ---------------------------------------------------------------------------
__global__ void scalars_kernel(const float* __restrict__ A_log,
                               const float* __restrict__ dt_bias)
{
    int i = blockIdx.x * blockDim.x + threadIdx.x;
    if (i >= BL * N_HEADS) return;
    int bl = i >> 4;
    int h  = i & 15;
    const float* row = g_proj + (size_t)bl * TOTAL_PROJ;
    float bv = row[12288 + h];
    g_beta[i] = 1.f / (1.f + expf(-bv));
    float a = row[12304 + h] + dt_bias[h];
    float sp = (a > 15.f) ? a : log1pf(expf(a));
    float g = -expf(A_log[h]) * sp;
    g_eg[i] = expf(g);
}

// ---------------------------------------------------------------------------
// Kernel 3: depthwise causal conv(4) + SiLU + per-head L2 norm (q,k only)
// grid: (64 channel-groups, 4096 (b,l)), 128 threads
// ---------------------------------------------------------------------------
__global__ __launch_bounds__(128) void conv_kernel(const float* __restrict__ Wconv)
{
    const int grp = blockIdx.x;           // 0..63 (group of 128 channels)
    const int bl  = blockIdx.y;           // 0..4095
    const int l   = bl & (L_SEQ - 1);
    const int c   = grp * 128 + threadIdx.x;     // 0..8191

    const float* w = Wconv + c * 4;
    const float w0 = w[0], w1 = w[1], w2 = w[2], w3 = w[3];
    const float* pbase = g_proj + (size_t)bl * TOTAL_PROJ + c;

    float acc = pbase[0] * w3;
    if (l >= 1) acc += pbase[-(ptrdiff_t)TOTAL_PROJ]     * w2;
    if (l >= 2) acc += pbase[-(ptrdiff_t)(2*TOTAL_PROJ)] * w1;
    if (l >= 3) acc += pbase[-(ptrdiff_t)(3*TOTAL_PROJ)] * w0;

    float s = acc / (1.f + expf(-acc));   // silu
    float val = s;

    __shared__ float red[128];
    if (grp < 32) {                       // q and k regions get L2-norm per 128
        red[threadIdx.x] = s * s;
        __syncthreads();
#pragma unroll
        for (int off = 64; off > 0; off >>= 1) {
            if (threadIdx.x < off) red[threadIdx.x] += red[threadIdx.x + off];
            __syncthreads();
        }
        val = s * rsqrtf(red[0] + 1e-6f);
    }
    g_y[(size_t)bl * CONV_CH + c] = val;
}

// ---------------------------------------------------------------------------
// Kernel 4: gated delta-rule recurrence + gate epilogue.
// Grid: 128 CTAs = (b,h) x 4 v-slices of 64 columns. 256 threads:
//   col = tid>>2 (0..63),  kp = tid&3 (32 k-values each).
// Thread state S[32] in registers. Shared k/q padded stride 33 (no bank conflicts).
// ---------------------------------------------------------------------------
__global__ __launch_bounds__(256, 1) void recurrence_kernel(float* __restrict__ out)
{
    const int slice = blockIdx.x & 3;
    const int bh    = blockIdx.x >> 2;
    const int b     = bh >> 4;
    const int h     = bh & 15;
    const int tid   = threadIdx.x;
    const int col   = tid >> 2;       // 0..63
    const int kp    = tid & 3;        // 0..3
    const int vcol  = slice * 64 + col;

    __shared__ float sk[2][132];
    __shared__ float sq[2][132];

    float S[32];
#pragma unroll
    for (int j = 0; j < 32; j++) S[j] = 0.f;

    const float scale = 0.08838834764831845f;   // 128^-0.5

    const size_t ybase = (size_t)b * L_SEQ * CONV_CH;
    const size_t pbase = (size_t)b * L_SEQ * TOTAL_PROJ;
    const int qofs = h * 128;
    const int kofs = KEY_DIM + h * 128;
    const int vofs = 2 * KEY_DIM + h * 256 + vcol;
    const int gofs = 2 * KEY_DIM + VALUE_DIM + h * 256 + vcol;
    const int ghofs = (b * L_SEQ) * N_HEADS + h;

    // prefetch t = 0
    float rk = 0.f, rq = 0.f;
    if (tid < 128) rk = g_y[ybase + kofs + tid];
    else           rq = g_y[ybase + qofs + (tid - 128)];
    float rv    = g_y[ybase + vofs];
    float rgate = g_proj[pbase + gofs];
    float reg_e = g_eg[ghofs];
    float rbeta = g_beta[ghofs];

    int buf = 0;
    for (int t = 0; t < L_SEQ; t++) {
        if (tid < 128) {
            sk[buf][(tid >> 5) * 33 + (tid & 31)] = rk;
        } else {
            int i = tid - 128;
            sq[buf][(i >> 5) * 33 + (i & 31)] = rq;
        }
        __syncthreads();

        const float eg = reg_e, bt = rbeta, vv = rv, gate = rgate;

        // prefetch t+1 (hidden under the compute below)
        if (t + 1 < L_SEQ) {
            const size_t yb = ybase + (size_t)(t + 1) * CONV_CH;
            if (tid < 128) rk = g_y[yb + kofs + tid];
            else           rq = g_y[yb + qofs + (tid - 128)];
            rv    = g_y[yb + vofs];
            rgate = g_proj[pbase + (size_t)(t + 1) * TOTAL_PROJ + gofs];
            reg_e = g_eg[ghofs + (t + 1) * N_HEADS];
            rbeta = g_beta[ghofs + (t + 1) * N_HEADS];
        }

        const float* skb = &sk[buf][kp * 33];
        const float* sqb = &sq[buf][kp * 33];

        // pass 1: partial kv = k . S_old
        float kv0 = 0.f, kv1 = 0.f, kv2 = 0.f, kv3 = 0.f;
#pragma unroll
        for (int j = 0; j < 32; j += 4) {
            kv0 += skb[j + 0] * S[j + 0];
            kv1 += skb[j + 1] * S[j + 1];
            kv2 += skb[j + 2] * S[j + 2];
            kv3 += skb[j + 3] * S[j + 3];
        }
        float kv = (kv0 + kv1) + (kv2 + kv3);
        kv += __shfl_xor_sync(0xffffffffu, kv, 1);
        kv += __shfl_xor_sync(0xffffffffu, kv, 2);

        const float delta = (vv - eg * kv) * bt;

        // pass 2: S = eg*S + k*delta, fused with qs = q . S_new
        float qs0 = 0.f, qs1 = 0.f, qs2 = 0.f, qs3 = 0.f;
#pragma unroll
        for (int j = 0; j < 32; j += 4) {
            float s0 = eg * S[j + 0] + skb[j + 0] * delta;
            float s1 = eg * S[j + 1] + skb[j + 1] * delta;
            float s2 = eg * S[j + 2] + skb[j + 2] * delta;
            float s3 = eg * S[j + 3] + skb[j + 3] * delta;
            S[j + 0] = s0; S[j + 1] = s1; S[j + 2] = s2; S[j + 3] = s3;
            qs0 += sqb[j + 0] * s0;
            qs1 += sqb[j + 1] * s1;
            qs2 += sqb[j + 2] * s2;
            qs3 += sqb[j + 3] * s3;
        }
        float qs = (qs0 + qs1) + (qs2 + qs3);
        qs += __shfl_xor_sync(0xffffffffu, qs, 1);
        qs += __shfl_xor_sync(0xffffffffu, qs, 2);

        if (kp == 0) {
            const float o  = qs * scale;
            const float sg = gate / (1.f + expf(-gate));
            out[((size_t)(b * L_SEQ + t) * N_HEADS + h) * HEAD_V + vcol] = o * sg;
        }
        buf ^= 1;
    }
}

// ---------------------------------------------------------------------------
// Launch
// ---------------------------------------------------------------------------
extern "C" void kernel_launch(void* const* d_in, const int* in_sizes, int n_in,
                              void* d_out, int out_size)
{
    const float* X       = (const float*)d_in[0];  // hidden_states [2,2048,2048]
    const float* W       = (const float*)d_in[1];  // W_qkvgba [2048,12320]
    const float* Wconv   = (const float*)d_in[2];  // [8192,4]
    const float* A_log   = (const float*)d_in[3];  // [16]
    const float* dt_bias = (const float*)d_in[4];  // [16]
    float* out = (float*)d_out;

    // 1) projection GEMM
    dim3 gemmGrid((TOTAL_PROJ + 127) / 128, BL / 128);   // (97, 32)
    sgemm_kernel<<<gemmGrid, 256>>>(X, W);

    // 2) eg / beta scalars
    scalars_kernel<<<(BL * N_HEADS + 255) / 256, 256>>>(A_log, dt_bias);

    // 3) conv + silu + l2norm
    dim3 convGrid(CONV_CH / 128, BL);                    // (64, 4096)
    conv_kernel<<<convGrid, 128>>>(Wconv);

    // 4) recurrence + gate epilogue
    recurrence_kernel<<<B_SZ * N_HEADS * 4, 256>>>(out);
}

// round 3
// speedup vs baseline: 1.9584x; 1.9584x over previous
#include <cuda_runtime.h>
#include <cuda_bf16.h>
#include <cstdint>

// ---------------------------------------------------------------------------
// Problem constants
// ---------------------------------------------------------------------------
#define B_SZ     2
#define L_SEQ    2048
#define D_MODEL  2048
#define N_HEADS  16
#define D_HEAD   128
#define HEAD_V   256
#define KEY_DIM  2048
#define VALUE_DIM 4096
#define TOTAL_PROJ 12320           // 2*2048 + 2*4096 + 2*16
#define CONV_CH  8192              // 2*KEY_DIM + VALUE_DIM
#define BL       (B_SZ * L_SEQ)    // 4096

// ---------------------------------------------------------------------------
// Scratch (static device globals; no allocation allowed)
// ---------------------------------------------------------------------------
__device__ float g_proj[(size_t)BL * TOTAL_PROJ];   // 4096 x 12320  (~202 MB)
__device__ float g_y[(size_t)BL * CONV_CH];         // 4096 x 8192   (~134 MB)
__device__ float g_eg[BL * N_HEADS];                // exp(g) per (b,l,h)
__device__ float g_beta[BL * N_HEADS];              // sigmoid(b)

// ---------------------------------------------------------------------------
// MMA helpers (legacy warp-level path; still present on sm_100a)
// ---------------------------------------------------------------------------
__device__ __forceinline__ uint32_t smem_u32(const void* p) {
    return (uint32_t)__cvta_generic_to_shared(p);
}
__device__ __forceinline__ void ldsm_x4(uint32_t& r0, uint32_t& r1,
                                        uint32_t& r2, uint32_t& r3, uint32_t a) {
    asm volatile("ldmatrix.sync.aligned.m8n8.x4.shared.b16 {%0,%1,%2,%3},[%4];\n"
                 : "=r"(r0), "=r"(r1), "=r"(r2), "=r"(r3) : "r"(a));
}
__device__ __forceinline__ void ldsm_x4_t(uint32_t& r0, uint32_t& r1,
                                          uint32_t& r2, uint32_t& r3, uint32_t a) {
    asm volatile("ldmatrix.sync.aligned.m8n8.x4.trans.shared.b16 {%0,%1,%2,%3},[%4];\n"
                 : "=r"(r0), "=r"(r1), "=r"(r2), "=r"(r3) : "r"(a));
}
__device__ __forceinline__ void mma_bf16(float* c, const uint32_t* a, const uint32_t* b) {
    asm volatile("mma.sync.aligned.m16n8k16.row.col.f32.bf16.bf16.f32 "
                 "{%0,%1,%2,%3},{%4,%5,%6,%7},{%8,%9},{%0,%1,%2,%3};\n"
                 : "+f"(c[0]), "+f"(c[1]), "+f"(c[2]), "+f"(c[3])
                 : "r"(a[0]), "r"(a[1]), "r"(a[2]), "r"(a[3]),
                   "r"(b[0]), "r"(b[1]));
}

// split: hi = top-16-bit truncation (exact), lo = bf16(x - hi)
// pack two floats' hi halves into one bf16x2 word with PRMT.
__device__ __forceinline__ uint32_t pack_hi2(float x0, float x1) {
    return __byte_perm(__float_as_uint(x0), __float_as_uint(x1), 0x7632);
}
__device__ __forceinline__ uint32_t pack_lo2(float x0, float x1) {
    float h0 = __uint_as_float(__float_as_uint(x0) & 0xffff0000u);
    float h1 = __uint_as_float(__float_as_uint(x1) & 0xffff0000u);
    __nv_bfloat162 l2 = __float22bfloat162_rn(make_float2(x0 - h0, x1 - h1));
    return *reinterpret_cast<uint32_t*>(&l2);
}

// ---------------------------------------------------------------------------
// Kernel 1: GEMM  proj = X[4096,2048] @ W[2048,12320]  via bf16x3 tensor-core
// 128x128 block tile, BK=16, 8 warps each 64x32, double-buffered smem.
// ---------------------------------------------------------------------------
__global__ __launch_bounds__(256) void mma_gemm_kernel(
    const float* __restrict__ A,     // [4096, 2048]
    const float* __restrict__ Bm)    // [2048, 12320]
{
    const int N = TOTAL_PROJ, K = D_MODEL;
    constexpr int AST = 24;    // A smem row stride (elems): 48B rows -> conflict-free LDSM
    constexpr int BST = 136;   // B smem row stride: 272B rows -> conflict-free LDSM

    __shared__ __nv_bfloat16 Ah[2][128 * AST];
    __shared__ __nv_bfloat16 Al[2][128 * AST];
    __shared__ __nv_bfloat16 Bh[2][16 * BST];
    __shared__ __nv_bfloat16 Bl[2][16 * BST];

    const int tid  = threadIdx.x;
    const int lane = tid & 31;
    const int warp = tid >> 5;
    const int wm   = warp & 1;      // 0..1 -> m offset 0/64
    const int wn   = warp >> 1;     // 0..3 -> n offset 0/32/64/96
    const int bx = blockIdx.x, by = blockIdx.y;
    const int colBase = bx * 128;

    // gmem load mapping (2 float4 per thread for A and for B)
    const int arow0 = tid >> 2;             // 0..63, +64
    const int acol  = (tid & 3) << 2;       // 0,4,8,12
    const int brow0 = tid >> 5;             // 0..7, +8
    const int bcol  = lane << 2;            // 0..124

    const float* Ag = A + (size_t)(by * 128) * K;

    float4 ra[2], rb[2];

    auto load_g = [&](int k0) {
#pragma unroll
        for (int i = 0; i < 2; i++) {
            ra[i] = *(const float4*)(Ag + (size_t)(arow0 + i * 64) * K + k0 + acol);
            const int gcol = colBase + bcol;
            const float* Brow = Bm + (size_t)(k0 + brow0 + i * 8) * N;
            if (gcol + 3 < N) {
                rb[i] = *(const float4*)(Brow + gcol);
            } else {
                rb[i].x = (gcol + 0 < N) ? Brow[gcol + 0] : 0.f;
                rb[i].y = (gcol + 1 < N) ? Brow[gcol + 1] : 0.f;
                rb[i].z = (gcol + 2 < N) ? Brow[gcol + 2] : 0.f;
                rb[i].w = (gcol + 3 < N) ? Brow[gcol + 3] : 0.f;
            }
        }
    };

    auto store_s = [&](int buf) {
#pragma unroll
        for (int i = 0; i < 2; i++) {
            const float* v = (const float*)&ra[i];
            const int abase = (arow0 + i * 64) * AST + acol;
            *(uint32_t*)&Ah[buf][abase + 0] = pack_hi2(v[0], v[1]);
            *(uint32_t*)&Ah[buf][abase + 2] = pack_hi2(v[2], v[3]);
            *(uint32_t*)&Al[buf][abase + 0] = pack_lo2(v[0], v[1]);
            *(uint32_t*)&Al[buf][abase + 2] = pack_lo2(v[2], v[3]);
            const float* w = (const float*)&rb[i];
            const int bbase = (brow0 + i * 8) * BST + bcol;
            *(uint32_t*)&Bh[buf][bbase + 0] = pack_hi2(w[0], w[1]);
            *(uint32_t*)&Bh[buf][bbase + 2] = pack_hi2(w[2], w[3]);
            *(uint32_t*)&Bl[buf][bbase + 0] = pack_lo2(w[0], w[1]);
            *(uint32_t*)&Bl[buf][bbase + 2] = pack_lo2(w[2], w[3]);
        }
    };

    float acc[4][4][4];
#pragma unroll
    for (int mt = 0; mt < 4; mt++)
#pragma unroll
        for (int nt = 0; nt < 4; nt++)
#pragma unroll
            for (int r = 0; r < 4; r++) acc[mt][nt][r] = 0.f;

    load_g(0);
    store_s(0);
    __syncthreads();

    const int m8 = lane >> 3;   // ldmatrix sub-matrix index 0..3
    const int j8 = lane & 7;

    for (int kt = 0; kt < K / 16; kt++) {
        const int buf = kt & 1;
        if (kt + 1 < K / 16) load_g((kt + 1) * 16);

        uint32_t ah[4][4], al[4][4], bh[4][2], bl[4][2];
        // A fragments: matrices ordered (r0-7,k0-7),(r8-15,k0-7),(r0-7,k8-15),(r8-15,k8-15)
#pragma unroll
        for (int mt = 0; mt < 4; mt++) {
            const int row = wm * 64 + mt * 16 + (m8 & 1) * 8 + j8;
            const int kc  = (m8 >> 1) * 8;
            ldsm_x4(ah[mt][0], ah[mt][1], ah[mt][2], ah[mt][3],
                    smem_u32(&Ah[buf][row * AST + kc]));
            ldsm_x4(al[mt][0], al[mt][1], al[mt][2], al[mt][3],
                    smem_u32(&Al[buf][row * AST + kc]));
        }
        // B fragments (trans): matrices (k0-7,n0-7),(k8-15,n0-7),(k0-7,n8-15),(k8-15,n8-15)
#pragma unroll
        for (int nt2 = 0; nt2 < 2; nt2++) {
            const int kk = (m8 & 1) * 8 + j8;
            const int nn = wn * 32 + nt2 * 16 + (m8 >> 1) * 8;
            uint32_t r0, r1, r2, r3;
            ldsm_x4_t(r0, r1, r2, r3, smem_u32(&Bh[buf][kk * BST + nn]));
            bh[nt2 * 2][0] = r0; bh[nt2 * 2][1] = r1;
            bh[nt2 * 2 + 1][0] = r2; bh[nt2 * 2 + 1][1] = r3;
            ldsm_x4_t(r0, r1, r2, r3, smem_u32(&Bl[buf][kk * BST + nn]));
            bl[nt2 * 2][0] = r0; bl[nt2 * 2][1] = r1;
            bl[nt2 * 2 + 1][0] = r2; bl[nt2 * 2 + 1][1] = r3;
        }

#pragma unroll
        for (int mt = 0; mt < 4; mt++)
#pragma unroll
            for (int nt = 0; nt < 4; nt++) {
                mma_bf16(acc[mt][nt], al[mt], bh[nt]);   // lo*hi
                mma_bf16(acc[mt][nt], ah[mt], bl[nt]);   // hi*lo
                mma_bf16(acc[mt][nt], ah[mt], bh[nt]);   // hi*hi
            }

        if (kt + 1 < K / 16) store_s(buf ^ 1);
        __syncthreads();
    }

    // epilogue: c0,c1 at row g, cols 2*tg..; c2,c3 at row g+8
    const int g4 = lane >> 2;
    const int tg = lane & 3;
#pragma unroll
    for (int mt = 0; mt < 4; mt++) {
        const int row0 = by * 128 + wm * 64 + mt * 16 + g4;
        float* C0 = g_proj + (size_t)row0 * N;
        float* C1 = g_proj + (size_t)(row0 + 8) * N;
#pragma unroll
        for (int nt = 0; nt < 4; nt++) {
            const int col = colBase + wn * 32 + nt * 8 + tg * 2;
            if (col < N) {
                *(float2*)(C0 + col) = make_float2(acc[mt][nt][0], acc[mt][nt][1]);
                *(float2*)(C1 + col) = make_float2(acc[mt][nt][2], acc[mt][nt][3]);
            }
        }
    }
}

// ---------------------------------------------------------------------------
// Kernel 2: per-(b,l,h) scalars:  eg = exp(g),  beta = sigmoid(b)
// ---------------------------------------------------------------------------
__global__ void scalars_kernel(const float* __restrict__ A_log,
                               const float* __restrict__ dt_bias)
{
    int i = blockIdx.x * blockDim.x + threadIdx.x;
    if (i >= BL * N_HEADS) return;
    int bl = i >> 4;
    int h  = i & 15;
    const float* row = g_proj + (size_t)bl * TOTAL_PROJ;
    float bv = row[12288 + h];
    g_beta[i] = 1.f / (1.f + expf(-bv));
    float a = row[12304 + h] + dt_bias[h];
    float sp = (a > 15.f) ? a : log1pf(expf(a));
    float g = -expf(A_log[h]) * sp;
    g_eg[i] = expf(g);
}

// ---------------------------------------------------------------------------
// Kernel 3: depthwise causal conv(4) + SiLU + per-head L2 norm (q,k only)
// grid: (64 channel-groups, 4096 (b,l)), 128 threads
// ---------------------------------------------------------------------------
__global__ __launch_bounds__(128) void conv_kernel(const float* __restrict__ Wconv)
{
    const int grp = blockIdx.x;           // 0..63 (group of 128 channels)
    const int bl  = blockIdx.y;           // 0..4095
    const int l   = bl & (L_SEQ - 1);
    const int c   = grp * 128 + threadIdx.x;     // 0..8191

    const float* w = Wconv + c * 4;
    const float w0 = w[0], w1 = w[1], w2 = w[2], w3 = w[3];
    const float* pbase = g_proj + (size_t)bl * TOTAL_PROJ + c;

    float acc = pbase[0] * w3;
    if (l >= 1) acc += pbase[-(ptrdiff_t)TOTAL_PROJ]     * w2;
    if (l >= 2) acc += pbase[-(ptrdiff_t)(2*TOTAL_PROJ)] * w1;
    if (l >= 3) acc += pbase[-(ptrdiff_t)(3*TOTAL_PROJ)] * w0;

    float s = acc / (1.f + expf(-acc));   // silu
    float val = s;

    __shared__ float red[128];
    if (grp < 32) {                       // q and k regions get L2-norm per 128
        red[threadIdx.x] = s * s;
        __syncthreads();
#pragma unroll
        for (int off = 64; off > 0; off >>= 1) {
            if (threadIdx.x < off) red[threadIdx.x] += red[threadIdx.x + off];
            __syncthreads();
        }
        val = s * rsqrtf(red[0] + 1e-6f);
    }
    g_y[(size_t)bl * CONV_CH + c] = val;
}

// ---------------------------------------------------------------------------
// Kernel 4: gated delta-rule recurrence + gate epilogue.
// Grid: 128 CTAs = (b,h) x 4 v-slices of 64 columns. 256 threads:
//   col = tid>>2 (0..63),  kp = tid&3 (32 k-values each).
// ---------------------------------------------------------------------------
__global__ __launch_bounds__(256, 1) void recurrence_kernel(float* __restrict__ out)
{
    const int slice = blockIdx.x & 3;
    const int bh    = blockIdx.x >> 2;
    const int b     = bh >> 4;
    const int h     = bh & 15;
    const int tid   = threadIdx.x;
    const int col   = tid >> 2;       // 0..63
    const int kp    = tid & 3;        // 0..3
    const int vcol  = slice * 64 + col;

    __shared__ float sk[2][132];
    __shared__ float sq[2][132];

    float S[32];
#pragma unroll
    for (int j = 0; j < 32; j++) S[j] = 0.f;

    const float scale = 0.08838834764831845f;   // 128^-0.5

    const size_t ybase = (size_t)b * L_SEQ * CONV_CH;
    const size_t pbase = (size_t)b * L_SEQ * TOTAL_PROJ;
    const int qofs = h * 128;
    const int kofs = KEY_DIM + h * 128;
    const int vofs = 2 * KEY_DIM + h * 256 + vcol;
    const int gofs = 2 * KEY_DIM + VALUE_DIM + h * 256 + vcol;
    const int ghofs = (b * L_SEQ) * N_HEADS + h;

    // prefetch t = 0
    float rk = 0.f, rq = 0.f;
    if (tid < 128) rk = g_y[ybase + kofs + tid];
    else           rq = g_y[ybase + qofs + (tid - 128)];
    float rv    = g_y[ybase + vofs];
    float rgate = g_proj[pbase + gofs];
    float reg_e = g_eg[ghofs];
    float rbeta = g_beta[ghofs];

    int buf = 0;
    for (int t = 0; t < L_SEQ; t++) {
        if (tid < 128) {
            sk[buf][(tid >> 5) * 33 + (tid & 31)] = rk;
        } else {
            int i = tid - 128;
            sq[buf][(i >> 5) * 33 + (i & 31)] = rq;
        }
        __syncthreads();

        const float eg = reg_e, bt = rbeta, vv = rv, gate = rgate;

        // prefetch t+1 (hidden under the compute below)
        if (t + 1 < L_SEQ) {
            const size_t yb = ybase + (size_t)(t + 1) * CONV_CH;
            if (tid < 128) rk = g_y[yb + kofs + tid];
            else           rq = g_y[yb + qofs + (tid - 128)];
            rv    = g_y[yb + vofs];
            rgate = g_proj[pbase + (size_t)(t + 1) * TOTAL_PROJ + gofs];
            reg_e = g_eg[ghofs + (t + 1) * N_HEADS];
            rbeta = g_beta[ghofs + (t + 1) * N_HEADS];
        }

        const float* skb = &sk[buf][kp * 33];
        const float* sqb = &sq[buf][kp * 33];

        // pass 1: partial kv = k . S_old
        float kv0 = 0.f, kv1 = 0.f, kv2 = 0.f, kv3 = 0.f;
#pragma unroll
        for (int j = 0; j < 32; j += 4) {
            kv0 += skb[j + 0] * S[j + 0];
            kv1 += skb[j + 1] * S[j + 1];
            kv2 += skb[j + 2] * S[j + 2];
            kv3 += skb[j + 3] * S[j + 3];
        }
        float kv = (kv0 + kv1) + (kv2 + kv3);
        kv += __shfl_xor_sync(0xffffffffu, kv, 1);
        kv += __shfl_xor_sync(0xffffffffu, kv, 2);

        const float delta = (vv - eg * kv) * bt;

        // pass 2: S = eg*S + k*delta, fused with qs = q . S_new
        float qs0 = 0.f, qs1 = 0.f, qs2 = 0.f, qs3 = 0.f;
#pragma unroll
        for (int j = 0; j < 32; j += 4) {
            float s0 = eg * S[j + 0] + skb[j + 0] * delta;
            float s1 = eg * S[j + 1] + skb[j + 1] * delta;
            float s2 = eg * S[j + 2] + skb[j + 2] * delta;
            float s3 = eg * S[j + 3] + skb[j + 3] * delta;
            S[j + 0] = s0; S[j + 1] = s1; S[j + 2] = s2; S[j + 3] = s3;
            qs0 += sqb[j + 0] * s0;
            qs1 += sqb[j + 1] * s1;
            qs2 += sqb[j + 2] * s2;
            qs3 += sqb[j + 3] * s3;
        }
        float qs = (qs0 + qs1) + (qs2 + qs3);
        qs += __shfl_xor_sync(0xffffffffu, qs, 1);
        qs += __shfl_xor_sync(0xffffffffu, qs, 2);

        if (kp == 0) {
            const float o  = qs * scale;
            const float sg = gate / (1.f + expf(-gate));
            out[((size_t)(b * L_SEQ + t) * N_HEADS + h) * HEAD_V + vcol] = o * sg;
        }
        buf ^= 1;
    }
}

// ---------------------------------------------------------------------------
// Launch
// ---------------------------------------------------------------------------
extern "C" void kernel_launch(void* const* d_in, const int* in_sizes, int n_in,
                              void* d_out, int out_size)
{
    const float* X       = (const float*)d_in[0];  // hidden_states [2,2048,2048]
    const float* W       = (const float*)d_in[1];  // W_qkvgba [2048,12320]
    const float* Wconv   = (const float*)d_in[2];  // [8192,4]
    const float* A_log   = (const float*)d_in[3];  // [16]
    const float* dt_bias = (const float*)d_in[4];  // [16]
    float* out = (float*)d_out;

    // 1) projection GEMM (bf16x3 tensor-core)
    dim3 gemmGrid((TOTAL_PROJ + 127) / 128, BL / 128);   // (97, 32)
    mma_gemm_kernel<<<gemmGrid, 256>>>(X, W);

    // 2) eg / beta scalars
    scalars_kernel<<<(BL * N_HEADS + 255) / 256, 256>>>(A_log, dt_bias);

    // 3) conv + silu + l2norm
    dim3 convGrid(CONV_CH / 128, BL);                    // (64, 4096)
    conv_kernel<<<convGrid, 128>>>(Wconv);

    // 4) recurrence + gate epilogue
    recurrence_kernel<<<B_SZ * N_HEADS * 4, 256>>>(out);
}

// round 4
// speedup vs baseline: 2.0332x; 1.0382x over previous
#include <cuda_runtime.h>
#include <cuda_bf16.h>
#include <cstdint>

// ---------------------------------------------------------------------------
// Problem constants
// ---------------------------------------------------------------------------
#define B_SZ     2
#define L_SEQ    2048
#define D_MODEL  2048
#define N_HEADS  16
#define D_HEAD   128
#define HEAD_V   256
#define KEY_DIM  2048
#define VALUE_DIM 4096
#define TOTAL_PROJ 12320           // 2*2048 + 2*4096 + 2*16
#define CONV_CH  8192              // 2*KEY_DIM + VALUE_DIM
#define BL       (B_SZ * L_SEQ)    // 4096

// ---------------------------------------------------------------------------
// Scratch (static device globals; no allocation allowed)
// ---------------------------------------------------------------------------
__device__ float g_proj[(size_t)BL * TOTAL_PROJ];   // 4096 x 12320  (~202 MB)
__device__ float g_y[(size_t)BL * CONV_CH];         // 4096 x 8192   (~134 MB)
__device__ float g_eg[BL * N_HEADS];                // exp(g)
__device__ float g_beta[BL * N_HEADS];              // sigmoid(b)

// pre-split bf16 hi/lo operands
__device__ __nv_bfloat16 g_Ah[(size_t)BL * D_MODEL];
__device__ __nv_bfloat16 g_Al[(size_t)BL * D_MODEL];
__device__ __nv_bfloat16 g_Bh[(size_t)D_MODEL * TOTAL_PROJ];
__device__ __nv_bfloat16 g_Bl[(size_t)D_MODEL * TOTAL_PROJ];

// ---------------------------------------------------------------------------
// Helpers
// ---------------------------------------------------------------------------
__device__ __forceinline__ uint32_t smem_u32(const void* p) {
    return (uint32_t)__cvta_generic_to_shared(p);
}
__device__ __forceinline__ void ldsm_x4(uint32_t& r0, uint32_t& r1,
                                        uint32_t& r2, uint32_t& r3, uint32_t a) {
    asm volatile("ldmatrix.sync.aligned.m8n8.x4.shared.b16 {%0,%1,%2,%3},[%4];\n"
                 : "=r"(r0), "=r"(r1), "=r"(r2), "=r"(r3) : "r"(a));
}
__device__ __forceinline__ void ldsm_x4_t(uint32_t& r0, uint32_t& r1,
                                          uint32_t& r2, uint32_t& r3, uint32_t a) {
    asm volatile("ldmatrix.sync.aligned.m8n8.x4.trans.shared.b16 {%0,%1,%2,%3},[%4];\n"
                 : "=r"(r0), "=r"(r1), "=r"(r2), "=r"(r3) : "r"(a));
}
__device__ __forceinline__ void mma_bf16(float* c, const uint32_t* a, const uint32_t* b) {
    asm volatile("mma.sync.aligned.m16n8k16.row.col.f32.bf16.bf16.f32 "
                 "{%0,%1,%2,%3},{%4,%5,%6,%7},{%8,%9},{%0,%1,%2,%3};\n"
                 : "+f"(c[0]), "+f"(c[1]), "+f"(c[2]), "+f"(c[3])
                 : "r"(a[0]), "r"(a[1]), "r"(a[2]), "r"(a[3]),
                   "r"(b[0]), "r"(b[1]));
}
__device__ __forceinline__ uint32_t pack_hi2(float x0, float x1) {
    return __byte_perm(__float_as_uint(x0), __float_as_uint(x1), 0x7632);
}
__device__ __forceinline__ uint32_t pack_lo2(float x0, float x1) {
    float h0 = __uint_as_float(__float_as_uint(x0) & 0xffff0000u);
    float h1 = __uint_as_float(__float_as_uint(x1) & 0xffff0000u);
    __nv_bfloat162 l2 = __float22bfloat162_rn(make_float2(x0 - h0, x1 - h1));
    return *reinterpret_cast<uint32_t*>(&l2);
}
__device__ __forceinline__ void cp16(uint32_t dst, const void* src) {
    asm volatile("cp.async.cg.shared.global [%0], [%1], 16;\n"
                 :: "r"(dst), "l"(src));
}

// ---------------------------------------------------------------------------
// Kernel 0: split fp32 -> bf16 hi/lo for A (hidden) and B (W_qkvgba)
// ---------------------------------------------------------------------------
#define NA4 ((size_t)BL * D_MODEL / 4)             // 2,097,152
#define NB4 ((size_t)D_MODEL * TOTAL_PROJ / 4)     // 6,307,840
__global__ __launch_bounds__(256) void split_kernel(
    const float* __restrict__ A, const float* __restrict__ Bm)
{
    const size_t total = NA4 + NB4;
    for (size_t i = (size_t)blockIdx.x * blockDim.x + threadIdx.x;
         i < total; i += (size_t)gridDim.x * blockDim.x) {
        if (i < NA4) {
            float4 v = ((const float4*)A)[i];
            uint2 hi = make_uint2(pack_hi2(v.x, v.y), pack_hi2(v.z, v.w));
            uint2 lo = make_uint2(pack_lo2(v.x, v.y), pack_lo2(v.z, v.w));
            ((uint2*)g_Ah)[i] = hi;
            ((uint2*)g_Al)[i] = lo;
        } else {
            size_t j = i - NA4;
            float4 v = ((const float4*)Bm)[j];
            uint2 hi = make_uint2(pack_hi2(v.x, v.y), pack_hi2(v.z, v.w));
            uint2 lo = make_uint2(pack_lo2(v.x, v.y), pack_lo2(v.z, v.w));
            ((uint2*)g_Bh)[j] = hi;
            ((uint2*)g_Bl)[j] = lo;
        }
    }
}

// ---------------------------------------------------------------------------
// Kernel 1: GEMM  proj = X[4096,2048] @ W[2048,12320], bf16x3, cp.async x4
// grid (32 Mtiles, 97 Ntiles); 128x128 tile, BK=16, 8 warps of 64x32.
// ---------------------------------------------------------------------------
#define STAGES 4
#define AST 24     // A smem row stride (elems)
#define BST 136    // B smem row stride (elems)
#define A_BYTES (128 * AST * 2)          // 6144
#define B_BYTES (16 * BST * 2)           // 4352
#define STAGE_BYTES (2 * A_BYTES + 2 * B_BYTES)   // 20992
#define SMEM_TOTAL_GEMM (STAGES * STAGE_BYTES)    // 83968

__global__ __launch_bounds__(256) void mma_gemm_kernel()
{
    const int N = TOTAL_PROJ, K = D_MODEL;
    extern __shared__ __align__(16) char smem_raw[];

    const int tid  = threadIdx.x;
    const int lane = tid & 31;
    const int warp = tid >> 5;
    const int wm   = warp & 1;
    const int wn   = warp >> 1;
    const int mtile = blockIdx.x;          // 0..31
    const int colBase = blockIdx.y * 128;  // 0..96*128

    const int mrow0 = mtile * 128;

    // copy mappings
    const int ar = tid >> 1;               // 0..127
    const int ac = (tid & 1) << 3;         // 0 or 8 (elems)
    const int br = tid >> 4;               // 0..15
    const int bc = (tid & 15) << 3;        // 0..120 (elems)
    const bool bvalid = (colBase + bc) < N;

    auto sAh = [&](int s) { return (__nv_bfloat16*)(smem_raw + s * STAGE_BYTES); };
    auto sAl = [&](int s) { return (__nv_bfloat16*)(smem_raw + s * STAGE_BYTES + A_BYTES); };
    auto sBh = [&](int s) { return (__nv_bfloat16*)(smem_raw + s * STAGE_BYTES + 2 * A_BYTES); };
    auto sBl = [&](int s) { return (__nv_bfloat16*)(smem_raw + s * STAGE_BYTES + 2 * A_BYTES + B_BYTES); };

    auto copy_stage = [&](int s, int kt) {
        const int k0 = kt * 16;
        cp16(smem_u32(sAh(s) + ar * AST + ac), g_Ah + (size_t)(mrow0 + ar) * K + k0 + ac);
        cp16(smem_u32(sAl(s) + ar * AST + ac), g_Al + (size_t)(mrow0 + ar) * K + k0 + ac);
        if (bvalid) {
            cp16(smem_u32(sBh(s) + br * BST + bc), g_Bh + (size_t)(k0 + br) * N + colBase + bc);
            cp16(smem_u32(sBl(s) + br * BST + bc), g_Bl + (size_t)(k0 + br) * N + colBase + bc);
        } else {
            uint4 z = make_uint4(0, 0, 0, 0);
            *(uint4*)(sBh(s) + br * BST + bc) = z;
            *(uint4*)(sBl(s) + br * BST + bc) = z;
        }
    };

    float acc[4][4][4];
#pragma unroll
    for (int mt = 0; mt < 4; mt++)
#pragma unroll
        for (int nt = 0; nt < 4; nt++)
#pragma unroll
            for (int r = 0; r < 4; r++) acc[mt][nt][r] = 0.f;

    const int KT = K / 16;   // 128
#pragma unroll
    for (int s = 0; s < STAGES - 1; s++) {
        copy_stage(s, s);
        asm volatile("cp.async.commit_group;\n" ::: "memory");
    }

    const int m8 = lane >> 3;
    const int j8 = lane & 7;

    for (int kt = 0; kt < KT; kt++) {
        asm volatile("cp.async.wait_group %0;\n" :: "n"(STAGES - 2) : "memory");
        __syncthreads();

        const int nk = kt + STAGES - 1;
        if (nk < KT) copy_stage(nk & (STAGES - 1), nk);
        asm volatile("cp.async.commit_group;\n" ::: "memory");

        const int buf = kt & (STAGES - 1);
        const __nv_bfloat16* Ahs = sAh(buf);
        const __nv_bfloat16* Als = sAl(buf);
        const __nv_bfloat16* Bhs = sBh(buf);
        const __nv_bfloat16* Bls = sBl(buf);

        uint32_t ah[4][4], al[4][4], bh[4][2], bl[4][2];
#pragma unroll
        for (int mt = 0; mt < 4; mt++) {
            const int row = wm * 64 + mt * 16 + (m8 & 1) * 8 + j8;
            const int kc  = (m8 >> 1) * 8;
            ldsm_x4(ah[mt][0], ah[mt][1], ah[mt][2], ah[mt][3],
                    smem_u32(Ahs + row * AST + kc));
            ldsm_x4(al[mt][0], al[mt][1], al[mt][2], al[mt][3],
                    smem_u32(Als + row * AST + kc));
        }
#pragma unroll
        for (int nt2 = 0; nt2 < 2; nt2++) {
            const int kk = (m8 & 1) * 8 + j8;
            const int nn = wn * 32 + nt2 * 16 + (m8 >> 1) * 8;
            uint32_t r0, r1, r2, r3;
            ldsm_x4_t(r0, r1, r2, r3, smem_u32(Bhs + kk * BST + nn));
            bh[nt2 * 2][0] = r0; bh[nt2 * 2][1] = r1;
            bh[nt2 * 2 + 1][0] = r2; bh[nt2 * 2 + 1][1] = r3;
            ldsm_x4_t(r0, r1, r2, r3, smem_u32(Bls + kk * BST + nn));
            bl[nt2 * 2][0] = r0; bl[nt2 * 2][1] = r1;
            bl[nt2 * 2 + 1][0] = r2; bl[nt2 * 2 + 1][1] = r3;
        }

#pragma unroll
        for (int mt = 0; mt < 4; mt++)
#pragma unroll
            for (int nt = 0; nt < 4; nt++) {
                mma_bf16(acc[mt][nt], al[mt], bh[nt]);
                mma_bf16(acc[mt][nt], ah[mt], bl[nt]);
                mma_bf16(acc[mt][nt], ah[mt], bh[nt]);
            }
        __syncthreads();
    }

    // epilogue
    const int g4 = lane >> 2;
    const int tg = lane & 3;
#pragma unroll
    for (int mt = 0; mt < 4; mt++) {
        const int row0 = mrow0 + wm * 64 + mt * 16 + g4;
        float* C0 = g_proj + (size_t)row0 * N;
        float* C1 = g_proj + (size_t)(row0 + 8) * N;
#pragma unroll
        for (int nt = 0; nt < 4; nt++) {
            const int col = colBase + wn * 32 + nt * 8 + tg * 2;
            if (col < N) {
                *(float2*)(C0 + col) = make_float2(acc[mt][nt][0], acc[mt][nt][1]);
                *(float2*)(C1 + col) = make_float2(acc[mt][nt][2], acc[mt][nt][3]);
            }
        }
    }
}

// ---------------------------------------------------------------------------
// Kernel 2: per-(b,l,h) scalars
// ---------------------------------------------------------------------------
__global__ void scalars_kernel(const float* __restrict__ A_log,
                               const float* __restrict__ dt_bias)
{
    int i = blockIdx.x * blockDim.x + threadIdx.x;
    if (i >= BL * N_HEADS) return;
    int bl = i >> 4;
    int h  = i & 15;
    const float* row = g_proj + (size_t)bl * TOTAL_PROJ;
    float bv = row[12288 + h];
    g_beta[i] = 1.f / (1.f + expf(-bv));
    float a = row[12304 + h] + dt_bias[h];
    float sp = (a > 15.f) ? a : log1pf(expf(a));
    float g = -expf(A_log[h]) * sp;
    g_eg[i] = expf(g);
}

// ---------------------------------------------------------------------------
// Kernel 3: depthwise causal conv(4) + SiLU + per-head L2 norm (q,k only)
// ---------------------------------------------------------------------------
__global__ __launch_bounds__(128) void conv_kernel(const float* __restrict__ Wconv)
{
    const int grp = blockIdx.x;
    const int bl  = blockIdx.y;
    const int l   = bl & (L_SEQ - 1);
    const int c   = grp * 128 + threadIdx.x;

    const float* w = Wconv + c * 4;
    const float w0 = w[0], w1 = w[1], w2 = w[2], w3 = w[3];
    const float* pbase = g_proj + (size_t)bl * TOTAL_PROJ + c;

    float acc = pbase[0] * w3;
    if (l >= 1) acc += pbase[-(ptrdiff_t)TOTAL_PROJ]     * w2;
    if (l >= 2) acc += pbase[-(ptrdiff_t)(2*TOTAL_PROJ)] * w1;
    if (l >= 3) acc += pbase[-(ptrdiff_t)(3*TOTAL_PROJ)] * w0;

    float s = acc / (1.f + expf(-acc));
    float val = s;

    __shared__ float red[128];
    if (grp < 32) {
        red[threadIdx.x] = s * s;
        __syncthreads();
#pragma unroll
        for (int off = 64; off > 0; off >>= 1) {
            if (threadIdx.x < off) red[threadIdx.x] += red[threadIdx.x + off];
            __syncthreads();
        }
        val = s * rsqrtf(red[0] + 1e-6f);
    }
    g_y[(size_t)bl * CONV_CH + c] = val;
}

// ---------------------------------------------------------------------------
// Kernel 4: gated delta-rule recurrence + gate epilogue.
// ---------------------------------------------------------------------------
__global__ __launch_bounds__(256, 1) void recurrence_kernel(float* __restrict__ out)
{
    const int slice = blockIdx.x & 3;
    const int bh    = blockIdx.x >> 2;
    const int b     = bh >> 4;
    const int h     = bh & 15;
    const int tid   = threadIdx.x;
    const int col   = tid >> 2;
    const int kp    = tid & 3;
    const int vcol  = slice * 64 + col;

    __shared__ float sk[2][132];
    __shared__ float sq[2][132];

    float S[32];
#pragma unroll
    for (int j = 0; j < 32; j++) S[j] = 0.f;

    const float scale = 0.08838834764831845f;

    const size_t ybase = (size_t)b * L_SEQ * CONV_CH;
    const size_t pbase = (size_t)b * L_SEQ * TOTAL_PROJ;
    const int qofs = h * 128;
    const int kofs = KEY_DIM + h * 128;
    const int vofs = 2 * KEY_DIM + h * 256 + vcol;
    const int gofs = 2 * KEY_DIM + VALUE_DIM + h * 256 + vcol;
    const int ghofs = (b * L_SEQ) * N_HEADS + h;

    float rk = 0.f, rq = 0.f;
    if (tid < 128) rk = g_y[ybase + kofs + tid];
    else           rq = g_y[ybase + qofs + (tid - 128)];
    float rv    = g_y[ybase + vofs];
    float rgate = g_proj[pbase + gofs];
    float reg_e = g_eg[ghofs];
    float rbeta = g_beta[ghofs];

    int buf = 0;
    for (int t = 0; t < L_SEQ; t++) {
        if (tid < 128) {
            sk[buf][(tid >> 5) * 33 + (tid & 31)] = rk;
        } else {
            int i = tid - 128;
            sq[buf][(i >> 5) * 33 + (i & 31)] = rq;
        }
        __syncthreads();

        const float eg = reg_e, bt = rbeta, vv = rv, gate = rgate;

        if (t + 1 < L_SEQ) {
            const size_t yb = ybase + (size_t)(t + 1) * CONV_CH;
            if (tid < 128) rk = g_y[yb + kofs + tid];
            else           rq = g_y[yb + qofs + (tid - 128)];
            rv    = g_y[yb + vofs];
            rgate = g_proj[pbase + (size_t)(t + 1) * TOTAL_PROJ + gofs];
            reg_e = g_eg[ghofs + (t + 1) * N_HEADS];
            rbeta = g_beta[ghofs + (t + 1) * N_HEADS];
        }

        const float* skb = &sk[buf][kp * 33];
        const float* sqb = &sq[buf][kp * 33];

        float kv0 = 0.f, kv1 = 0.f, kv2 = 0.f, kv3 = 0.f;
#pragma unroll
        for (int j = 0; j < 32; j += 4) {
            kv0 += skb[j + 0] * S[j + 0];
            kv1 += skb[j + 1] * S[j + 1];
            kv2 += skb[j + 2] * S[j + 2];
            kv3 += skb[j + 3] * S[j + 3];
        }
        float kv = (kv0 + kv1) + (kv2 + kv3);
        kv += __shfl_xor_sync(0xffffffffu, kv, 1);
        kv += __shfl_xor_sync(0xffffffffu, kv, 2);

        const float delta = (vv - eg * kv) * bt;

        float qs0 = 0.f, qs1 = 0.f, qs2 = 0.f, qs3 = 0.f;
#pragma unroll
        for (int j = 0; j < 32; j += 4) {
            float s0 = eg * S[j + 0] + skb[j + 0] * delta;
            float s1 = eg * S[j + 1] + skb[j + 1] * delta;
            float s2 = eg * S[j + 2] + skb[j + 2] * delta;
            float s3 = eg * S[j + 3] + skb[j + 3] * delta;
            S[j + 0] = s0; S[j + 1] = s1; S[j + 2] = s2; S[j + 3] = s3;
            qs0 += sqb[j + 0] * s0;
            qs1 += sqb[j + 1] * s1;
            qs2 += sqb[j + 2] * s2;
            qs3 += sqb[j + 3] * s3;
        }
        float qs = (qs0 + qs1) + (qs2 + qs3);
        qs += __shfl_xor_sync(0xffffffffu, qs, 1);
        qs += __shfl_xor_sync(0xffffffffu, qs, 2);

        if (kp == 0) {
            const float o  = qs * scale;
            const float sg = gate / (1.f + expf(-gate));
            out[((size_t)(b * L_SEQ + t) * N_HEADS + h) * HEAD_V + vcol] = o * sg;
        }
        buf ^= 1;
    }
}

// ---------------------------------------------------------------------------
// Launch
// ---------------------------------------------------------------------------
extern "C" void kernel_launch(void* const* d_in, const int* in_sizes, int n_in,
                              void* d_out, int out_size)
{
    const float* X       = (const float*)d_in[0];
    const float* W       = (const float*)d_in[1];
    const float* Wconv   = (const float*)d_in[2];
    const float* A_log   = (const float*)d_in[3];
    const float* dt_bias = (const float*)d_in[4];
    float* out = (float*)d_out;

    // allow >48KB dynamic smem for the GEMM (idempotent; host-side attr set)
    cudaFuncSetAttribute(mma_gemm_kernel,
                         cudaFuncAttributeMaxDynamicSharedMemorySize,
                         SMEM_TOTAL_GEMM);

    // 0) split operands into bf16 hi/lo
    split_kernel<<<2048, 256>>>(X, W);

    // 1) projection GEMM
    dim3 gemmGrid(BL / 128, (TOTAL_PROJ + 127) / 128);   // (32, 97)
    mma_gemm_kernel<<<gemmGrid, 256, SMEM_TOTAL_GEMM>>>();

    // 2) eg / beta scalars
    scalars_kernel<<<(BL * N_HEADS + 255) / 256, 256>>>(A_log, dt_bias);

    // 3) conv + silu + l2norm
    dim3 convGrid(CONV_CH / 128, BL);
    conv_kernel<<<convGrid, 128>>>(Wconv);

    // 4) recurrence + gate epilogue
    recurrence_kernel<<<B_SZ * N_HEADS * 4, 256>>>(out);
}

// round 6
// speedup vs baseline: 2.2216x; 1.0926x over previous
#include <cuda_runtime.h>
#include <cuda_bf16.h>
#include <cstdint>

// ---------------------------------------------------------------------------
// Problem constants
// ---------------------------------------------------------------------------
#define B_SZ     2
#define L_SEQ    2048
#define D_MODEL  2048
#define N_HEADS  16
#define D_HEAD   128
#define HEAD_V   256
#define KEY_DIM  2048
#define VALUE_DIM 4096
#define TOTAL_PROJ 12320           // 2*2048 + 2*4096 + 2*16
#define CONV_CH  8192              // 2*KEY_DIM + VALUE_DIM
#define BL       (B_SZ * L_SEQ)    // 4096

// ---------------------------------------------------------------------------
// Scratch (static device globals; no allocation allowed)
// ---------------------------------------------------------------------------
__device__ float g_proj[(size_t)BL * TOTAL_PROJ];   // 4096 x 12320  (~202 MB)
__device__ float g_y[(size_t)BL * CONV_CH];         // 4096 x 8192   (~134 MB)
__device__ float g_eg[BL * N_HEADS];                // exp(g)
__device__ float g_beta[BL * N_HEADS];              // sigmoid(b)

// pre-split bf16 hi/lo operands
__device__ __nv_bfloat16 g_Ah[(size_t)BL * D_MODEL];
__device__ __nv_bfloat16 g_Al[(size_t)BL * D_MODEL];
__device__ __nv_bfloat16 g_Bh[(size_t)D_MODEL * TOTAL_PROJ];
__device__ __nv_bfloat16 g_Bl[(size_t)D_MODEL * TOTAL_PROJ];

// ---------------------------------------------------------------------------
// Helpers
// ---------------------------------------------------------------------------
__device__ __forceinline__ uint32_t smem_u32(const void* p) {
    return (uint32_t)__cvta_generic_to_shared(p);
}
__device__ __forceinline__ void ldsm_x4(uint32_t& r0, uint32_t& r1,
                                        uint32_t& r2, uint32_t& r3, uint32_t a) {
    asm volatile("ldmatrix.sync.aligned.m8n8.x4.shared.b16 {%0,%1,%2,%3},[%4];\n"
                 : "=r"(r0), "=r"(r1), "=r"(r2), "=r"(r3) : "r"(a));
}
__device__ __forceinline__ void ldsm_x4_t(uint32_t& r0, uint32_t& r1,
                                          uint32_t& r2, uint32_t& r3, uint32_t a) {
    asm volatile("ldmatrix.sync.aligned.m8n8.x4.trans.shared.b16 {%0,%1,%2,%3},[%4];\n"
                 : "=r"(r0), "=r"(r1), "=r"(r2), "=r"(r3) : "r"(a));
}
__device__ __forceinline__ void mma_bf16(float* c, const uint32_t* a, const uint32_t* b) {
    asm volatile("mma.sync.aligned.m16n8k16.row.col.f32.bf16.bf16.f32 "
                 "{%0,%1,%2,%3},{%4,%5,%6,%7},{%8,%9},{%0,%1,%2,%3};\n"
                 : "+f"(c[0]), "+f"(c[1]), "+f"(c[2]), "+f"(c[3])
                 : "r"(a[0]), "r"(a[1]), "r"(a[2]), "r"(a[3]),
                   "r"(b[0]), "r"(b[1]));
}
__device__ __forceinline__ uint32_t pack_hi2(float x0, float x1) {
    return __byte_perm(__float_as_uint(x0), __float_as_uint(x1), 0x7632);
}
__device__ __forceinline__ uint32_t pack_lo2(float x0, float x1) {
    float h0 = __uint_as_float(__float_as_uint(x0) & 0xffff0000u);
    float h1 = __uint_as_float(__float_as_uint(x1) & 0xffff0000u);
    __nv_bfloat162 l2 = __float22bfloat162_rn(make_float2(x0 - h0, x1 - h1));
    return *reinterpret_cast<uint32_t*>(&l2);
}
__device__ __forceinline__ void cp16(uint32_t dst, const void* src) {
    asm volatile("cp.async.cg.shared.global [%0], [%1], 16;\n"
                 :: "r"(dst), "l"(src));
}
__device__ __forceinline__ void cp4(uint32_t dst, const void* src) {
    asm volatile("cp.async.ca.shared.global [%0], [%1], 4;\n"
                 :: "r"(dst), "l"(src));
}

// ---------------------------------------------------------------------------
// Kernel 0: split fp32 -> bf16 hi/lo for A (hidden) and B (W_qkvgba)
// ---------------------------------------------------------------------------
#define NA4 ((size_t)BL * D_MODEL / 4)             // 2,097,152
#define NB4 ((size_t)D_MODEL * TOTAL_PROJ / 4)     // 6,307,840
__global__ __launch_bounds__(256) void split_kernel(
    const float* __restrict__ A, const float* __restrict__ Bm)
{
    const size_t total = NA4 + NB4;
    for (size_t i = (size_t)blockIdx.x * blockDim.x + threadIdx.x;
         i < total; i += (size_t)gridDim.x * blockDim.x) {
        if (i < NA4) {
            float4 v = ((const float4*)A)[i];
            uint2 hi = make_uint2(pack_hi2(v.x, v.y), pack_hi2(v.z, v.w));
            uint2 lo = make_uint2(pack_lo2(v.x, v.y), pack_lo2(v.z, v.w));
            ((uint2*)g_Ah)[i] = hi;
            ((uint2*)g_Al)[i] = lo;
        } else {
            size_t j = i - NA4;
            float4 v = ((const float4*)Bm)[j];
            uint2 hi = make_uint2(pack_hi2(v.x, v.y), pack_hi2(v.z, v.w));
            uint2 lo = make_uint2(pack_lo2(v.x, v.y), pack_lo2(v.z, v.w));
            ((uint2*)g_Bh)[j] = hi;
            ((uint2*)g_Bl)[j] = lo;
        }
    }
}

// ---------------------------------------------------------------------------
// Kernel 1: GEMM  proj = X[4096,2048] @ W[2048,12320], bf16x3, cp.async x4
// ---------------------------------------------------------------------------
#define STAGES 4
#define AST 24
#define BST 136
#define A_BYTES (128 * AST * 2)
#define B_BYTES (16 * BST * 2)
#define STAGE_BYTES (2 * A_BYTES + 2 * B_BYTES)
#define SMEM_TOTAL_GEMM (STAGES * STAGE_BYTES)

__global__ __launch_bounds__(256) void mma_gemm_kernel()
{
    const int N = TOTAL_PROJ, K = D_MODEL;
    extern __shared__ __align__(16) char smem_raw[];

    const int tid  = threadIdx.x;
    const int lane = tid & 31;
    const int warp = tid >> 5;
    const int wm   = warp & 1;
    const int wn   = warp >> 1;
    const int mtile = blockIdx.x;
    const int colBase = blockIdx.y * 128;

    const int mrow0 = mtile * 128;

    const int ar = tid >> 1;
    const int ac = (tid & 1) << 3;
    const int br = tid >> 4;
    const int bc = (tid & 15) << 3;
    const bool bvalid = (colBase + bc) < N;

    auto sAh = [&](int s) { return (__nv_bfloat16*)(smem_raw + s * STAGE_BYTES); };
    auto sAl = [&](int s) { return (__nv_bfloat16*)(smem_raw + s * STAGE_BYTES + A_BYTES); };
    auto sBh = [&](int s) { return (__nv_bfloat16*)(smem_raw + s * STAGE_BYTES + 2 * A_BYTES); };
    auto sBl = [&](int s) { return (__nv_bfloat16*)(smem_raw + s * STAGE_BYTES + 2 * A_BYTES + B_BYTES); };

    auto copy_stage = [&](int s, int kt) {
        const int k0 = kt * 16;
        cp16(smem_u32(sAh(s) + ar * AST + ac), g_Ah + (size_t)(mrow0 + ar) * K + k0 + ac);
        cp16(smem_u32(sAl(s) + ar * AST + ac), g_Al + (size_t)(mrow0 + ar) * K + k0 + ac);
        if (bvalid) {
            cp16(smem_u32(sBh(s) + br * BST + bc), g_Bh + (size_t)(k0 + br) * N + colBase + bc);
            cp16(smem_u32(sBl(s) + br * BST + bc), g_Bl + (size_t)(k0 + br) * N + colBase + bc);
        } else {
            uint4 z = make_uint4(0, 0, 0, 0);
            *(uint4*)(sBh(s) + br * BST + bc) = z;
            *(uint4*)(sBl(s) + br * BST + bc) = z;
        }
    };

    float acc[4][4][4];
#pragma unroll
    for (int mt = 0; mt < 4; mt++)
#pragma unroll
        for (int nt = 0; nt < 4; nt++)
#pragma unroll
            for (int r = 0; r < 4; r++) acc[mt][nt][r] = 0.f;

    const int KT = K / 16;
#pragma unroll
    for (int s = 0; s < STAGES - 1; s++) {
        copy_stage(s, s);
        asm volatile("cp.async.commit_group;\n" ::: "memory");
    }

    const int m8 = lane >> 3;
    const int j8 = lane & 7;

    for (int kt = 0; kt < KT; kt++) {
        asm volatile("cp.async.wait_group %0;\n" :: "n"(STAGES - 2) : "memory");
        __syncthreads();

        const int nk = kt + STAGES - 1;
        if (nk < KT) copy_stage(nk & (STAGES - 1), nk);
        asm volatile("cp.async.commit_group;\n" ::: "memory");

        const int buf = kt & (STAGES - 1);
        const __nv_bfloat16* Ahs = sAh(buf);
        const __nv_bfloat16* Als = sAl(buf);
        const __nv_bfloat16* Bhs = sBh(buf);
        const __nv_bfloat16* Bls = sBl(buf);

        uint32_t ah[4][4], al[4][4], bh[4][2], bl[4][2];
#pragma unroll
        for (int mt = 0; mt < 4; mt++) {
            const int row = wm * 64 + mt * 16 + (m8 & 1) * 8 + j8;
            const int kc  = (m8 >> 1) * 8;
            ldsm_x4(ah[mt][0], ah[mt][1], ah[mt][2], ah[mt][3],
                    smem_u32(Ahs + row * AST + kc));
            ldsm_x4(al[mt][0], al[mt][1], al[mt][2], al[mt][3],
                    smem_u32(Als + row * AST + kc));
        }
#pragma unroll
        for (int nt2 = 0; nt2 < 2; nt2++) {
            const int kk = (m8 & 1) * 8 + j8;
            const int nn = wn * 32 + nt2 * 16 + (m8 >> 1) * 8;
            uint32_t r0, r1, r2, r3;
            ldsm_x4_t(r0, r1, r2, r3, smem_u32(Bhs + kk * BST + nn));
            bh[nt2 * 2][0] = r0; bh[nt2 * 2][1] = r1;
            bh[nt2 * 2 + 1][0] = r2; bh[nt2 * 2 + 1][1] = r3;
            ldsm_x4_t(r0, r1, r2, r3, smem_u32(Bls + kk * BST + nn));
            bl[nt2 * 2][0] = r0; bl[nt2 * 2][1] = r1;
            bl[nt2 * 2 + 1][0] = r2; bl[nt2 * 2 + 1][1] = r3;
        }

#pragma unroll
        for (int mt = 0; mt < 4; mt++)
#pragma unroll
            for (int nt = 0; nt < 4; nt++) {
                mma_bf16(acc[mt][nt], al[mt], bh[nt]);
                mma_bf16(acc[mt][nt], ah[mt], bl[nt]);
                mma_bf16(acc[mt][nt], ah[mt], bh[nt]);
            }
        __syncthreads();
    }

    const int g4 = lane >> 2;
    const int tg = lane & 3;
#pragma unroll
    for (int mt = 0; mt < 4; mt++) {
        const int row0 = mrow0 + wm * 64 + mt * 16 + g4;
        float* C0 = g_proj + (size_t)row0 * N;
        float* C1 = g_proj + (size_t)(row0 + 8) * N;
#pragma unroll
        for (int nt = 0; nt < 4; nt++) {
            const int col = colBase + wn * 32 + nt * 8 + tg * 2;
            if (col < N) {
                *(float2*)(C0 + col) = make_float2(acc[mt][nt][0], acc[mt][nt][1]);
                *(float2*)(C1 + col) = make_float2(acc[mt][nt][2], acc[mt][nt][3]);
            }
        }
    }
}

// ---------------------------------------------------------------------------
// Kernel 2: per-(b,l,h) scalars
// ---------------------------------------------------------------------------
__global__ void scalars_kernel(const float* __restrict__ A_log,
                               const float* __restrict__ dt_bias)
{
    int i = blockIdx.x * blockDim.x + threadIdx.x;
    if (i >= BL * N_HEADS) return;
    int bl = i >> 4;
    int h  = i & 15;
    const float* row = g_proj + (size_t)bl * TOTAL_PROJ;
    float bv = row[12288 + h];
    g_beta[i] = 1.f / (1.f + expf(-bv));
    float a = row[12304 + h] + dt_bias[h];
    float sp = (a > 15.f) ? a : log1pf(expf(a));
    float g = -expf(A_log[h]) * sp;
    g_eg[i] = expf(g);
}

// ---------------------------------------------------------------------------
// Kernel 3: depthwise causal conv(4) + SiLU + per-head L2 norm (q,k only)
// ---------------------------------------------------------------------------
__global__ __launch_bounds__(128) void conv_kernel(const float* __restrict__ Wconv)
{
    const int grp = blockIdx.x;
    const int bl  = blockIdx.y;
    const int l   = bl & (L_SEQ - 1);
    const int c   = grp * 128 + threadIdx.x;

    const float* w = Wconv + c * 4;
    const float w0 = w[0], w1 = w[1], w2 = w[2], w3 = w[3];
    const float* pbase = g_proj + (size_t)bl * TOTAL_PROJ + c;

    float acc = pbase[0] * w3;
    if (l >= 1) acc += pbase[-(ptrdiff_t)TOTAL_PROJ]     * w2;
    if (l >= 2) acc += pbase[-(ptrdiff_t)(2*TOTAL_PROJ)] * w1;
    if (l >= 3) acc += pbase[-(ptrdiff_t)(3*TOTAL_PROJ)] * w0;

    float s = acc / (1.f + expf(-acc));
    float val = s;

    __shared__ float red[128];
    if (grp < 32) {
        red[threadIdx.x] = s * s;
        __syncthreads();
#pragma unroll
        for (int off = 64; off > 0; off >>= 1) {
            if (threadIdx.x < off) red[threadIdx.x] += red[threadIdx.x + off];
            __syncthreads();
        }
        val = s * rsqrtf(red[0] + 1e-6f);
    }
    g_y[(size_t)bl * CONV_CH + c] = val;
}

// ---------------------------------------------------------------------------
// Kernel 4: gated delta-rule recurrence, cp.async 8-stage ring.
// Grid: 128 CTAs = (b,h) x 4 v-slices of 64 cols. 256 threads:
//   col = tid>>2 (0..63), kp = tid&3; thread owns S rows j = kp + 4*i.
// Stage layout (floats): k[0..127] q[128..255] v[256..319] gate[320..383]
//                        eg[384] beta[385]; stride 392.
// ---------------------------------------------------------------------------
#define RDEPTH 8
#define RSTRIDE 392

__global__ __launch_bounds__(256, 1) void recurrence_kernel(float* __restrict__ out)
{
    const int slice = blockIdx.x & 3;
    const int bh    = blockIdx.x >> 2;
    const int b     = bh >> 4;
    const int h     = bh & 15;
    const int tid   = threadIdx.x;
    const int col   = tid >> 2;
    const int kp    = tid & 3;
    const int vcol  = slice * 64 + col;

    __shared__ __align__(16) float ring[RDEPTH * RSTRIDE];

    float S[32];
#pragma unroll
    for (int j = 0; j < 32; j++) S[j] = 0.f;

    const float scale = 0.08838834764831845f;   // 128^-0.5

    const size_t ybase = (size_t)b * L_SEQ * CONV_CH;
    const size_t pbase = (size_t)b * L_SEQ * TOTAL_PROJ;
    const int qofs  = h * 128;
    const int kofs  = KEY_DIM + h * 128;
    const int vofs0 = 2 * KEY_DIM + h * 256 + slice * 64;
    const int gofs0 = 2 * KEY_DIM + VALUE_DIM + h * 256 + slice * 64;
    const int ghofs = (b * L_SEQ) * N_HEADS + h;

    const uint32_t ring_u32 = smem_u32(ring);

    auto issue_stage = [&](int t) {
        const uint32_t sb = ring_u32 + (uint32_t)((t & (RDEPTH - 1)) * RSTRIDE * 4);
        const size_t yb = ybase + (size_t)t * CONV_CH;
        if (tid < 32) {
            cp16(sb + (uint32_t)(tid * 16), g_y + yb + kofs + tid * 4);
        } else if (tid < 64) {
            const int i = tid - 32;
            cp16(sb + (uint32_t)(128 * 4 + i * 16), g_y + yb + qofs + i * 4);
        } else if (tid < 80) {
            const int i = tid - 64;
            cp16(sb + (uint32_t)(256 * 4 + i * 16), g_y + yb + vofs0 + i * 4);
        } else if (tid < 96) {
            const int i = tid - 80;
            cp16(sb + (uint32_t)(320 * 4 + i * 16),
                 g_proj + pbase + (size_t)t * TOTAL_PROJ + gofs0 + i * 4);
        } else if (tid == 96) {
            cp4(sb + 384 * 4, g_eg + ghofs + t * N_HEADS);
        } else if (tid == 97) {
            cp4(sb + 385 * 4, g_beta + ghofs + t * N_HEADS);
        }
    };

    // preload stages 0..RDEPTH-2
#pragma unroll
    for (int s = 0; s < RDEPTH - 1; s++) {
        issue_stage(s);
        asm volatile("cp.async.commit_group;\n" ::: "memory");
    }

    for (int t = 0; t < L_SEQ; t++) {
        asm volatile("cp.async.wait_group %0;\n" :: "n"(RDEPTH - 2) : "memory");
        __syncthreads();

        // refill slot (t-1)%8 with stage t+7 (consumed last iteration)
        if (t + RDEPTH - 1 < L_SEQ) issue_stage(t + RDEPTH - 1);
        asm volatile("cp.async.commit_group;\n" ::: "memory");

        const float* sb = ring + (t & (RDEPTH - 1)) * RSTRIDE;
        const float eg   = sb[384];
        const float bt   = sb[385];
        const float vv   = sb[256 + col];
        const float gate = sb[320 + col];
        const float* kk = sb + kp;          // k[kp + 4i]
        const float* qq = sb + 128 + kp;    // q[kp + 4i]

        // pass 1: kv = k . S_old  (keep k in registers for pass 2)
        float kreg[32];
        float kv0 = 0.f, kv1 = 0.f, kv2 = 0.f, kv3 = 0.f;
#pragma unroll
        for (int i = 0; i < 32; i += 4) {
            kreg[i + 0] = kk[4 * (i + 0)];
            kreg[i + 1] = kk[4 * (i + 1)];
            kreg[i + 2] = kk[4 * (i + 2)];
            kreg[i + 3] = kk[4 * (i + 3)];
            kv0 += kreg[i + 0] * S[i + 0];
            kv1 += kreg[i + 1] * S[i + 1];
            kv2 += kreg[i + 2] * S[i + 2];
            kv3 += kreg[i + 3] * S[i + 3];
        }
        float kv = (kv0 + kv1) + (kv2 + kv3);
        kv += __shfl_xor_sync(0xffffffffu, kv, 1);
        kv += __shfl_xor_sync(0xffffffffu, kv, 2);

        const float delta = (vv - eg * kv) * bt;

        // pass 2: S = eg*S + k*delta, fused with qs = q . S_new
        float qs0 = 0.f, qs1 = 0.f, qs2 = 0.f, qs3 = 0.f;
#pragma unroll
        for (int i = 0; i < 32; i += 4) {
            float s0 = eg * S[i + 0] + kreg[i + 0] * delta;
            float s1 = eg * S[i + 1] + kreg[i + 1] * delta;
            float s2 = eg * S[i + 2] + kreg[i + 2] * delta;
            float s3 = eg * S[i + 3] + kreg[i + 3] * delta;
            S[i + 0] = s0; S[i + 1] = s1; S[i + 2] = s2; S[i + 3] = s3;
            qs0 += qq[4 * (i + 0)] * s0;
            qs1 += qq[4 * (i + 1)] * s1;
            qs2 += qq[4 * (i + 2)] * s2;
            qs3 += qq[4 * (i + 3)] * s3;
        }
        float qs = (qs0 + qs1) + (qs2 + qs3);
        qs += __shfl_xor_sync(0xffffffffu, qs, 1);
        qs += __shfl_xor_sync(0xffffffffu, qs, 2);

        if (kp == 0) {
            const float o  = qs * scale;
            const float sg = gate / (1.f + expf(-gate));
            out[((size_t)(b * L_SEQ + t) * N_HEADS + h) * HEAD_V + vcol] = o * sg;
        }
    }
}

// ---------------------------------------------------------------------------
// Launch
// ---------------------------------------------------------------------------
extern "C" void kernel_launch(void* const* d_in, const int* in_sizes, int n_in,
                              void* d_out, int out_size)
{
    const float* X       = (const float*)d_in[0];
    const float* W       = (const float*)d_in[1];
    const float* Wconv   = (const float*)d_in[2];
    const float* A_log   = (const float*)d_in[3];
    const float* dt_bias = (const float*)d_in[4];
    float* out = (float*)d_out;

    cudaFuncSetAttribute(mma_gemm_kernel,
                         cudaFuncAttributeMaxDynamicSharedMemorySize,
                         SMEM_TOTAL_GEMM);

    split_kernel<<<2048, 256>>>(X, W);

    dim3 gemmGrid(BL / 128, (TOTAL_PROJ + 127) / 128);
    mma_gemm_kernel<<<gemmGrid, 256, SMEM_TOTAL_GEMM>>>();

    scalars_kernel<<<(BL * N_HEADS + 255) / 256, 256>>>(A_log, dt_bias);

    dim3 convGrid(CONV_CH / 128, BL);
    conv_kernel<<<convGrid, 128>>>(Wconv);

    recurrence_kernel<<<B_SZ * N_HEADS * 4, 256>>>(out);
}

// round 7
// speedup vs baseline: 2.3389x; 1.0528x over previous
#include <cuda_runtime.h>
#include <cuda_bf16.h>
#include <cstdint>

// ---------------------------------------------------------------------------
// Problem constants
// ---------------------------------------------------------------------------
#define B_SZ     2
#define L_SEQ    2048
#define D_MODEL  2048
#define N_HEADS  16
#define D_HEAD   128
#define HEAD_V   256
#define KEY_DIM  2048
#define VALUE_DIM 4096
#define TOTAL_PROJ 12320           // 2*2048 + 2*4096 + 2*16
#define CONV_CH  8192              // 2*KEY_DIM + VALUE_DIM
#define BL       (B_SZ * L_SEQ)    // 4096

// ---------------------------------------------------------------------------
// Scratch (static device globals; no allocation allowed)
// ---------------------------------------------------------------------------
__device__ float g_proj[(size_t)BL * TOTAL_PROJ];   // 4096 x 12320  (~202 MB)
__device__ float g_y[(size_t)BL * CONV_CH];         // 4096 x 8192   (~134 MB)
__device__ float g_eg[BL * N_HEADS];                // exp(g)
__device__ float g_beta[BL * N_HEADS];              // sigmoid(b)

// pre-split bf16 hi/lo operands
__device__ __nv_bfloat16 g_Ah[(size_t)BL * D_MODEL];
__device__ __nv_bfloat16 g_Al[(size_t)BL * D_MODEL];
__device__ __nv_bfloat16 g_Bh[(size_t)D_MODEL * TOTAL_PROJ];
__device__ __nv_bfloat16 g_Bl[(size_t)D_MODEL * TOTAL_PROJ];

// ---------------------------------------------------------------------------
// Helpers
// ---------------------------------------------------------------------------
__device__ __forceinline__ uint32_t smem_u32(const void* p) {
    return (uint32_t)__cvta_generic_to_shared(p);
}
__device__ __forceinline__ void ldsm_x4(uint32_t& r0, uint32_t& r1,
                                        uint32_t& r2, uint32_t& r3, uint32_t a) {
    asm volatile("ldmatrix.sync.aligned.m8n8.x4.shared.b16 {%0,%1,%2,%3},[%4];\n"
                 : "=r"(r0), "=r"(r1), "=r"(r2), "=r"(r3) : "r"(a));
}
__device__ __forceinline__ void ldsm_x4_t(uint32_t& r0, uint32_t& r1,
                                          uint32_t& r2, uint32_t& r3, uint32_t a) {
    asm volatile("ldmatrix.sync.aligned.m8n8.x4.trans.shared.b16 {%0,%1,%2,%3},[%4];\n"
                 : "=r"(r0), "=r"(r1), "=r"(r2), "=r"(r3) : "r"(a));
}
__device__ __forceinline__ void mma_bf16(float* c, const uint32_t* a, const uint32_t* b) {
    asm volatile("mma.sync.aligned.m16n8k16.row.col.f32.bf16.bf16.f32 "
                 "{%0,%1,%2,%3},{%4,%5,%6,%7},{%8,%9},{%0,%1,%2,%3};\n"
                 : "+f"(c[0]), "+f"(c[1]), "+f"(c[2]), "+f"(c[3])
                 : "r"(a[0]), "r"(a[1]), "r"(a[2]), "r"(a[3]),
                   "r"(b[0]), "r"(b[1]));
}
__device__ __forceinline__ uint32_t pack_hi2(float x0, float x1) {
    return __byte_perm(__float_as_uint(x0), __float_as_uint(x1), 0x7632);
}
__device__ __forceinline__ uint32_t pack_lo2(float x0, float x1) {
    float h0 = __uint_as_float(__float_as_uint(x0) & 0xffff0000u);
    float h1 = __uint_as_float(__float_as_uint(x1) & 0xffff0000u);
    __nv_bfloat162 l2 = __float22bfloat162_rn(make_float2(x0 - h0, x1 - h1));
    return *reinterpret_cast<uint32_t*>(&l2);
}
__device__ __forceinline__ void cp16(uint32_t dst, const void* src) {
    asm volatile("cp.async.cg.shared.global [%0], [%1], 16;\n"
                 :: "r"(dst), "l"(src));
}
__device__ __forceinline__ void cp4(uint32_t dst, const void* src) {
    asm volatile("cp.async.ca.shared.global [%0], [%1], 4;\n"
                 :: "r"(dst), "l"(src));
}

// ---------------------------------------------------------------------------
// Kernel 0: split fp32 -> bf16 hi/lo for A (hidden) and B (W_qkvgba)
// ---------------------------------------------------------------------------
#define NA4 ((size_t)BL * D_MODEL / 4)
#define NB4 ((size_t)D_MODEL * TOTAL_PROJ / 4)
__global__ __launch_bounds__(256) void split_kernel(
    const float* __restrict__ A, const float* __restrict__ Bm)
{
    const size_t total = NA4 + NB4;
    for (size_t i = (size_t)blockIdx.x * blockDim.x + threadIdx.x;
         i < total; i += (size_t)gridDim.x * blockDim.x) {
        if (i < NA4) {
            float4 v = ((const float4*)A)[i];
            uint2 hi = make_uint2(pack_hi2(v.x, v.y), pack_hi2(v.z, v.w));
            uint2 lo = make_uint2(pack_lo2(v.x, v.y), pack_lo2(v.z, v.w));
            ((uint2*)g_Ah)[i] = hi;
            ((uint2*)g_Al)[i] = lo;
        } else {
            size_t j = i - NA4;
            float4 v = ((const float4*)Bm)[j];
            uint2 hi = make_uint2(pack_hi2(v.x, v.y), pack_hi2(v.z, v.w));
            uint2 lo = make_uint2(pack_lo2(v.x, v.y), pack_lo2(v.z, v.w));
            ((uint2*)g_Bh)[j] = hi;
            ((uint2*)g_Bl)[j] = lo;
        }
    }
}

// ---------------------------------------------------------------------------
// Kernel 1: GEMM  proj = X[4096,2048] @ W[2048,12320], bf16x3, cp.async x4
// ---------------------------------------------------------------------------
#define STAGES 4
#define AST 24
#define BST 136
#define A_BYTES (128 * AST * 2)
#define B_BYTES (16 * BST * 2)
#define STAGE_BYTES (2 * A_BYTES + 2 * B_BYTES)
#define SMEM_TOTAL_GEMM (STAGES * STAGE_BYTES)

__global__ __launch_bounds__(256) void mma_gemm_kernel()
{
    const int N = TOTAL_PROJ, K = D_MODEL;
    extern __shared__ __align__(16) char smem_raw[];

    const int tid  = threadIdx.x;
    const int lane = tid & 31;
    const int warp = tid >> 5;
    const int wm   = warp & 1;
    const int wn   = warp >> 1;
    const int mtile = blockIdx.x;
    const int colBase = blockIdx.y * 128;

    const int mrow0 = mtile * 128;

    const int ar = tid >> 1;
    const int ac = (tid & 1) << 3;
    const int br = tid >> 4;
    const int bc = (tid & 15) << 3;
    const bool bvalid = (colBase + bc) < N;

    auto sAh = [&](int s) { return (__nv_bfloat16*)(smem_raw + s * STAGE_BYTES); };
    auto sAl = [&](int s) { return (__nv_bfloat16*)(smem_raw + s * STAGE_BYTES + A_BYTES); };
    auto sBh = [&](int s) { return (__nv_bfloat16*)(smem_raw + s * STAGE_BYTES + 2 * A_BYTES); };
    auto sBl = [&](int s) { return (__nv_bfloat16*)(smem_raw + s * STAGE_BYTES + 2 * A_BYTES + B_BYTES); };

    auto copy_stage = [&](int s, int kt) {
        const int k0 = kt * 16;
        cp16(smem_u32(sAh(s) + ar * AST + ac), g_Ah + (size_t)(mrow0 + ar) * K + k0 + ac);
        cp16(smem_u32(sAl(s) + ar * AST + ac), g_Al + (size_t)(mrow0 + ar) * K + k0 + ac);
        if (bvalid) {
            cp16(smem_u32(sBh(s) + br * BST + bc), g_Bh + (size_t)(k0 + br) * N + colBase + bc);
            cp16(smem_u32(sBl(s) + br * BST + bc), g_Bl + (size_t)(k0 + br) * N + colBase + bc);
        } else {
            uint4 z = make_uint4(0, 0, 0, 0);
            *(uint4*)(sBh(s) + br * BST + bc) = z;
            *(uint4*)(sBl(s) + br * BST + bc) = z;
        }
    };

    float acc[4][4][4];
#pragma unroll
    for (int mt = 0; mt < 4; mt++)
#pragma unroll
        for (int nt = 0; nt < 4; nt++)
#pragma unroll
            for (int r = 0; r < 4; r++) acc[mt][nt][r] = 0.f;

    const int KT = K / 16;
#pragma unroll
    for (int s = 0; s < STAGES - 1; s++) {
        copy_stage(s, s);
        asm volatile("cp.async.commit_group;\n" ::: "memory");
    }

    const int m8 = lane >> 3;
    const int j8 = lane & 7;

    for (int kt = 0; kt < KT; kt++) {
        asm volatile("cp.async.wait_group %0;\n" :: "n"(STAGES - 2) : "memory");
        __syncthreads();

        const int nk = kt + STAGES - 1;
        if (nk < KT) copy_stage(nk & (STAGES - 1), nk);
        asm volatile("cp.async.commit_group;\n" ::: "memory");

        const int buf = kt & (STAGES - 1);
        const __nv_bfloat16* Ahs = sAh(buf);
        const __nv_bfloat16* Als = sAl(buf);
        const __nv_bfloat16* Bhs = sBh(buf);
        const __nv_bfloat16* Bls = sBl(buf);

        uint32_t ah[4][4], al[4][4], bh[4][2], bl[4][2];
#pragma unroll
        for (int mt = 0; mt < 4; mt++) {
            const int row = wm * 64 + mt * 16 + (m8 & 1) * 8 + j8;
            const int kc  = (m8 >> 1) * 8;
            ldsm_x4(ah[mt][0], ah[mt][1], ah[mt][2], ah[mt][3],
                    smem_u32(Ahs + row * AST + kc));
            ldsm_x4(al[mt][0], al[mt][1], al[mt][2], al[mt][3],
                    smem_u32(Als + row * AST + kc));
        }
#pragma unroll
        for (int nt2 = 0; nt2 < 2; nt2++) {
            const int kk = (m8 & 1) * 8 + j8;
            const int nn = wn * 32 + nt2 * 16 + (m8 >> 1) * 8;
            uint32_t r0, r1, r2, r3;
            ldsm_x4_t(r0, r1, r2, r3, smem_u32(Bhs + kk * BST + nn));
            bh[nt2 * 2][0] = r0; bh[nt2 * 2][1] = r1;
            bh[nt2 * 2 + 1][0] = r2; bh[nt2 * 2 + 1][1] = r3;
            ldsm_x4_t(r0, r1, r2, r3, smem_u32(Bls + kk * BST + nn));
            bl[nt2 * 2][0] = r0; bl[nt2 * 2][1] = r1;
            bl[nt2 * 2 + 1][0] = r2; bl[nt2 * 2 + 1][1] = r3;
        }

#pragma unroll
        for (int mt = 0; mt < 4; mt++)
#pragma unroll
            for (int nt = 0; nt < 4; nt++) {
                mma_bf16(acc[mt][nt], al[mt], bh[nt]);
                mma_bf16(acc[mt][nt], ah[mt], bl[nt]);
                mma_bf16(acc[mt][nt], ah[mt], bh[nt]);
            }
        __syncthreads();
    }

    const int g4 = lane >> 2;
    const int tg = lane & 3;
#pragma unroll
    for (int mt = 0; mt < 4; mt++) {
        const int row0 = mrow0 + wm * 64 + mt * 16 + g4;
        float* C0 = g_proj + (size_t)row0 * N;
        float* C1 = g_proj + (size_t)(row0 + 8) * N;
#pragma unroll
        for (int nt = 0; nt < 4; nt++) {
            const int col = colBase + wn * 32 + nt * 8 + tg * 2;
            if (col < N) {
                *(float2*)(C0 + col) = make_float2(acc[mt][nt][0], acc[mt][nt][1]);
                *(float2*)(C1 + col) = make_float2(acc[mt][nt][2], acc[mt][nt][3]);
            }
        }
    }
}

// ---------------------------------------------------------------------------
// Kernel 2: per-(b,l,h) scalars
// ---------------------------------------------------------------------------
__global__ void scalars_kernel(const float* __restrict__ A_log,
                               const float* __restrict__ dt_bias)
{
    int i = blockIdx.x * blockDim.x + threadIdx.x;
    if (i >= BL * N_HEADS) return;
    int bl = i >> 4;
    int h  = i & 15;
    const float* row = g_proj + (size_t)bl * TOTAL_PROJ;
    float bv = row[12288 + h];
    g_beta[i] = 1.f / (1.f + expf(-bv));
    float a = row[12304 + h] + dt_bias[h];
    float sp = (a > 15.f) ? a : log1pf(expf(a));
    float g = -expf(A_log[h]) * sp;
    g_eg[i] = expf(g);
}

// ---------------------------------------------------------------------------
// Kernel 3: depthwise causal conv(4) + SiLU + per-head L2 norm (q,k only)
// l-tiled by 8: each CTA loads 11 proj rows (registers), emits 8 outputs.
// grid: (64 channel-groups, BL/8), 128 threads.
// ---------------------------------------------------------------------------
#define CTILE 8
__global__ __launch_bounds__(128) void conv_kernel(const float* __restrict__ Wconv)
{
    const int grp  = blockIdx.x;                 // 0..63
    const int tile = blockIdx.y;                 // 0..511
    const int b    = tile / (L_SEQ / CTILE);
    const int l0   = (tile % (L_SEQ / CTILE)) * CTILE;
    const int c    = grp * 128 + threadIdx.x;
    const int lane = threadIdx.x & 31;
    const int wid  = threadIdx.x >> 5;

    const float* w = Wconv + c * 4;
    const float w0 = w[0], w1 = w[1], w2 = w[2], w3 = w[3];

    // xv[j] = proj[l0-3+j], j=0..10 (guard lower edge)
    const float* pbase = g_proj + ((size_t)(b * L_SEQ + l0)) * TOTAL_PROJ + c;
    float xv[CTILE + 3];
#pragma unroll
    for (int j = 0; j < CTILE + 3; j++) {
        const int l = l0 - 3 + j;
        xv[j] = (l >= 0) ? pbase[(ptrdiff_t)(j - 3) * TOTAL_PROJ] : 0.f;
    }

    __shared__ float red[4];
    float* yrow = g_y + ((size_t)(b * L_SEQ + l0)) * CONV_CH + c;

#pragma unroll
    for (int t = 0; t < CTILE; t++) {
        float acc = xv[t] * w0 + xv[t + 1] * w1 + xv[t + 2] * w2 + xv[t + 3] * w3;
        float s = acc / (1.f + expf(-acc));   // silu
        float val = s;
        if (grp < 32) {                        // q/k: per-128-channel L2 norm
            float ss = s * s;
#pragma unroll
            for (int off = 16; off > 0; off >>= 1)
                ss += __shfl_xor_sync(0xffffffffu, ss, off);
            if (lane == 0) red[wid] = ss;
            __syncthreads();
            float tot = red[0] + red[1] + red[2] + red[3];
            val = s * rsqrtf(tot + 1e-6f);
            __syncthreads();
        }
        yrow[(size_t)t * CONV_CH] = val;
    }
}

// ---------------------------------------------------------------------------
// Kernel 4: gated delta-rule recurrence, cp.async 8-stage ring, LDS.128 reads.
// Grid: 128 CTAs = (b,h) x 4 v-slices of 64 cols. 256 threads:
//   col = tid>>2 (0..63), kp = tid&3; thread owns S rows kp*32 .. kp*32+31.
// Ring stage layout (floats), stride 420:
//   k  at [ (j>>5)*36 + (j&31) ]          (4 blocks of 36: bank-staggered)
//   q  at [ 144 + same mapping ]
//   v  at [288..351], gate at [352..415], eg at [416], beta at [417]
// ---------------------------------------------------------------------------
#define RDEPTH 8
#define RSTRIDE 420

__global__ __launch_bounds__(256, 1) void recurrence_kernel(float* __restrict__ out)
{
    const int slice = blockIdx.x & 3;
    const int bh    = blockIdx.x >> 2;
    const int b     = bh >> 4;
    const int h     = bh & 15;
    const int tid   = threadIdx.x;
    const int col   = tid >> 2;
    const int kp    = tid & 3;
    const int vcol  = slice * 64 + col;

    __shared__ __align__(16) float ring[RDEPTH * RSTRIDE];

    float S[32];
#pragma unroll
    for (int j = 0; j < 32; j++) S[j] = 0.f;

    const float scale = 0.08838834764831845f;   // 128^-0.5

    const size_t ybase = (size_t)b * L_SEQ * CONV_CH;
    const size_t pbase = (size_t)b * L_SEQ * TOTAL_PROJ;
    const int qofs  = h * 128;
    const int kofs  = KEY_DIM + h * 128;
    const int vofs0 = 2 * KEY_DIM + h * 256 + slice * 64;
    const int gofs0 = 2 * KEY_DIM + VALUE_DIM + h * 256 + slice * 64;
    const int ghofs = (b * L_SEQ) * N_HEADS + h;

    const uint32_t ring_u32 = smem_u32(ring);

    auto issue_stage = [&](int t) {
        const uint32_t sb = ring_u32 + (uint32_t)((t & (RDEPTH - 1)) * RSTRIDE * 4);
        const size_t yb = ybase + (size_t)t * CONV_CH;
        if (tid < 32) {
            const int j0 = tid * 4;                              // k rows j0..j0+3
            const uint32_t dst = (uint32_t)(((j0 >> 5) * 36 + (j0 & 31)) * 4);
            cp16(sb + dst, g_y + yb + kofs + j0);
        } else if (tid < 64) {
            const int j0 = (tid - 32) * 4;                       // q rows
            const uint32_t dst = (uint32_t)((144 + (j0 >> 5) * 36 + (j0 & 31)) * 4);
            cp16(sb + dst, g_y + yb + qofs + j0);
        } else if (tid < 80) {
            const int i = tid - 64;
            cp16(sb + (uint32_t)((288 + i * 4) * 4), g_y + yb + vofs0 + i * 4);
        } else if (tid < 96) {
            const int i = tid - 80;
            cp16(sb + (uint32_t)((352 + i * 4) * 4),
                 g_proj + pbase + (size_t)t * TOTAL_PROJ + gofs0 + i * 4);
        } else if (tid == 96) {
            cp4(sb + 416 * 4, g_eg + ghofs + t * N_HEADS);
        } else if (tid == 97) {
            cp4(sb + 417 * 4, g_beta + ghofs + t * N_HEADS);
        }
    };

#pragma unroll
    for (int s = 0; s < RDEPTH - 1; s++) {
        issue_stage(s);
        asm volatile("cp.async.commit_group;\n" ::: "memory");
    }

    for (int t = 0; t < L_SEQ; t++) {
        asm volatile("cp.async.wait_group %0;\n" :: "n"(RDEPTH - 2) : "memory");
        __syncthreads();

        if (t + RDEPTH - 1 < L_SEQ) issue_stage(t + RDEPTH - 1);
        asm volatile("cp.async.commit_group;\n" ::: "memory");

        const float* sb = ring + (t & (RDEPTH - 1)) * RSTRIDE;
        const float eg   = sb[416];
        const float bt   = sb[417];
        const float vv   = sb[288 + col];
        const float gate = sb[352 + col];
        const float4* k4 = (const float4*)(sb + kp * 36);
        const float4* q4 = (const float4*)(sb + 144 + kp * 36);

        // pass 1: kv = k . S_old (k kept in registers for pass 2)
        float kreg[32];
        float kv0 = 0.f, kv1 = 0.f, kv2 = 0.f, kv3 = 0.f;
#pragma unroll
        for (int i = 0; i < 8; i++) {
            float4 kv4 = k4[i];
            kreg[i * 4 + 0] = kv4.x; kreg[i * 4 + 1] = kv4.y;
            kreg[i * 4 + 2] = kv4.z; kreg[i * 4 + 3] = kv4.w;
            kv0 += kv4.x * S[i * 4 + 0];
            kv1 += kv4.y * S[i * 4 + 1];
            kv2 += kv4.z * S[i * 4 + 2];
            kv3 += kv4.w * S[i * 4 + 3];
        }
        float kv = (kv0 + kv1) + (kv2 + kv3);
        kv += __shfl_xor_sync(0xffffffffu, kv, 1);
        kv += __shfl_xor_sync(0xffffffffu, kv, 2);

        const float delta = (vv - eg * kv) * bt;

        // pass 2: S = eg*S + k*delta, fused with qs = q . S_new
        float qs0 = 0.f, qs1 = 0.f, qs2 = 0.f, qs3 = 0.f;
#pragma unroll
        for (int i = 0; i < 8; i++) {
            float4 qv4 = q4[i];
            float s0 = eg * S[i * 4 + 0] + kreg[i * 4 + 0] * delta;
            float s1 = eg * S[i * 4 + 1] + kreg[i * 4 + 1] * delta;
            float s2 = eg * S[i * 4 + 2] + kreg[i * 4 + 2] * delta;
            float s3 = eg * S[i * 4 + 3] + kreg[i * 4 + 3] * delta;
            S[i * 4 + 0] = s0; S[i * 4 + 1] = s1;
            S[i * 4 + 2] = s2; S[i * 4 + 3] = s3;
            qs0 += qv4.x * s0;
            qs1 += qv4.y * s1;
            qs2 += qv4.z * s2;
            qs3 += qv4.w * s3;
        }
        float qs = (qs0 + qs1) + (qs2 + qs3);
        qs += __shfl_xor_sync(0xffffffffu, qs, 1);
        qs += __shfl_xor_sync(0xffffffffu, qs, 2);

        if (kp == 0) {
            const float o  = qs * scale;
            const float sg = gate / (1.f + expf(-gate));
            out[((size_t)(b * L_SEQ + t) * N_HEADS + h) * HEAD_V + vcol] = o * sg;
        }
    }
}

// ---------------------------------------------------------------------------
// Launch
// ---------------------------------------------------------------------------
extern "C" void kernel_launch(void* const* d_in, const int* in_sizes, int n_in,
                              void* d_out, int out_size)
{
    const float* X       = (const float*)d_in[0];
    const float* W       = (const float*)d_in[1];
    const float* Wconv   = (const float*)d_in[2];
    const float* A_log   = (const float*)d_in[3];
    const float* dt_bias = (const float*)d_in[4];
    float* out = (float*)d_out;

    cudaFuncSetAttribute(mma_gemm_kernel,
                         cudaFuncAttributeMaxDynamicSharedMemorySize,
                         SMEM_TOTAL_GEMM);

    split_kernel<<<2048, 256>>>(X, W);

    dim3 gemmGrid(BL / 128, (TOTAL_PROJ + 127) / 128);
    mma_gemm_kernel<<<gemmGrid, 256, SMEM_TOTAL_GEMM>>>();

    scalars_kernel<<<(BL * N_HEADS + 255) / 256, 256>>>(A_log, dt_bias);

    dim3 convGrid(CONV_CH / 128, BL / CTILE);
    conv_kernel<<<convGrid, 128>>>(Wconv);

    recurrence_kernel<<<B_SZ * N_HEADS * 4, 256>>>(out);
}

// round 10
// speedup vs baseline: 2.4279x; 1.0380x over previous
#include <cuda_runtime.h>
#include <cuda_bf16.h>
#include <cstdint>

// ---------------------------------------------------------------------------
// Problem constants
// ---------------------------------------------------------------------------
#define B_SZ     2
#define L_SEQ    2048
#define D_MODEL  2048
#define N_HEADS  16
#define D_HEAD   128
#define HEAD_V   256
#define KEY_DIM  2048
#define VALUE_DIM 4096
#define TOTAL_PROJ 12320
#define CONV_CH  8192
#define BL       (B_SZ * L_SEQ)    // 4096

// ---------------------------------------------------------------------------
// Scratch (static device globals)
// ---------------------------------------------------------------------------
__device__ float g_proj[(size_t)BL * TOTAL_PROJ];
__device__ float g_y[(size_t)BL * CONV_CH];
__device__ float g_eg[BL * N_HEADS];
__device__ float g_beta[BL * N_HEADS];

// pre-split bf16 hi/lo operands (A row-major [4096x2048], B row-major [2048x12320])
__device__ __nv_bfloat16 g_Ah[(size_t)BL * D_MODEL];
__device__ __nv_bfloat16 g_Al[(size_t)BL * D_MODEL];
__device__ __nv_bfloat16 g_Bh[(size_t)D_MODEL * TOTAL_PROJ];
__device__ __nv_bfloat16 g_Bl[(size_t)D_MODEL * TOTAL_PROJ];

// ---------------------------------------------------------------------------
// Helpers
// ---------------------------------------------------------------------------
__device__ __forceinline__ uint32_t smem_u32(const void* p) {
    return (uint32_t)__cvta_generic_to_shared(p);
}
__device__ __forceinline__ void ldsm_x4(uint32_t& r0, uint32_t& r1,
                                        uint32_t& r2, uint32_t& r3, uint32_t a) {
    asm volatile("ldmatrix.sync.aligned.m8n8.x4.shared.b16 {%0,%1,%2,%3},[%4];\n"
                 : "=r"(r0), "=r"(r1), "=r"(r2), "=r"(r3) : "r"(a));
}
__device__ __forceinline__ void ldsm_x4_t(uint32_t& r0, uint32_t& r1,
                                          uint32_t& r2, uint32_t& r3, uint32_t a) {
    asm volatile("ldmatrix.sync.aligned.m8n8.x4.trans.shared.b16 {%0,%1,%2,%3},[%4];\n"
                 : "=r"(r0), "=r"(r1), "=r"(r2), "=r"(r3) : "r"(a));
}
__device__ __forceinline__ void mma_bf16(float* c, const uint32_t* a, const uint32_t* b) {
    asm volatile("mma.sync.aligned.m16n8k16.row.col.f32.bf16.bf16.f32 "
                 "{%0,%1,%2,%3},{%4,%5,%6,%7},{%8,%9},{%0,%1,%2,%3};\n"
                 : "+f"(c[0]), "+f"(c[1]), "+f"(c[2]), "+f"(c[3])
                 : "r"(a[0]), "r"(a[1]), "r"(a[2]), "r"(a[3]),
                   "r"(b[0]), "r"(b[1]));
}
__device__ __forceinline__ uint32_t pack_hi2(float x0, float x1) {
    return __byte_perm(__float_as_uint(x0), __float_as_uint(x1), 0x7632);
}
__device__ __forceinline__ uint32_t pack_lo2(float x0, float x1) {
    float h0 = __uint_as_float(__float_as_uint(x0) & 0xffff0000u);
    float h1 = __uint_as_float(__float_as_uint(x1) & 0xffff0000u);
    __nv_bfloat162 l2 = __float22bfloat162_rn(make_float2(x0 - h0, x1 - h1));
    return *reinterpret_cast<uint32_t*>(&l2);
}
__device__ __forceinline__ void cp16(uint32_t dst, const void* src) {
    asm volatile("cp.async.cg.shared.global [%0], [%1], 16;\n" :: "r"(dst), "l"(src));
}
__device__ __forceinline__ void cp4(uint32_t dst, const void* src) {
    asm volatile("cp.async.ca.shared.global [%0], [%1], 4;\n" :: "r"(dst), "l"(src));
}

// ---------------------------------------------------------------------------
// Kernel 0: split fp32 -> bf16 hi/lo for A (hidden) and B (W_qkvgba)
// ---------------------------------------------------------------------------
#define NA4 ((size_t)BL * D_MODEL / 4)
#define NB4 ((size_t)D_MODEL * TOTAL_PROJ / 4)
__global__ __launch_bounds__(256) void split_kernel(
    const float* __restrict__ A, const float* __restrict__ Bm)
{
    const size_t total = NA4 + NB4;
    for (size_t i = (size_t)blockIdx.x * blockDim.x + threadIdx.x;
         i < total; i += (size_t)gridDim.x * blockDim.x) {
        if (i < NA4) {
            float4 v = ((const float4*)A)[i];
            uint2 hi = make_uint2(pack_hi2(v.x, v.y), pack_hi2(v.z, v.w));
            uint2 lo = make_uint2(pack_lo2(v.x, v.y), pack_lo2(v.z, v.w));
            ((uint2*)g_Ah)[i] = hi;
            ((uint2*)g_Al)[i] = lo;
        } else {
            size_t j = i - NA4;
            float4 v = ((const float4*)Bm)[j];
            uint2 hi = make_uint2(pack_hi2(v.x, v.y), pack_hi2(v.z, v.w));
            uint2 lo = make_uint2(pack_lo2(v.x, v.y), pack_lo2(v.z, v.w));
            ((uint2*)g_Bh)[j] = hi;
            ((uint2*)g_Bl)[j] = lo;
        }
    }
}

// ---------------------------------------------------------------------------
// Kernel 1: GEMM  proj = X[4096,2048] @ W[2048,12320], bf16x3, cp.async x4
// (round-7 proven version)
// ---------------------------------------------------------------------------
#define STAGES 4
#define AST 24
#define BST 136
#define A_BYTES (128 * AST * 2)
#define B_BYTES (16 * BST * 2)
#define STAGE_BYTES (2 * A_BYTES + 2 * B_BYTES)
#define SMEM_TOTAL_GEMM (STAGES * STAGE_BYTES)

__global__ __launch_bounds__(256) void mma_gemm_kernel()
{
    const int N = TOTAL_PROJ, K = D_MODEL;
    extern __shared__ __align__(16) char smem_raw[];

    const int tid  = threadIdx.x;
    const int lane = tid & 31;
    const int warp = tid >> 5;
    const int wm   = warp & 1;
    const int wn   = warp >> 1;
    const int mtile = blockIdx.x;
    const int colBase = blockIdx.y * 128;

    const int mrow0 = mtile * 128;

    const int ar = tid >> 1;
    const int ac = (tid & 1) << 3;
    const int br = tid >> 4;
    const int bc = (tid & 15) << 3;
    const bool bvalid = (colBase + bc) < N;

    auto sAh = [&](int s) { return (__nv_bfloat16*)(smem_raw + s * STAGE_BYTES); };
    auto sAl = [&](int s) { return (__nv_bfloat16*)(smem_raw + s * STAGE_BYTES + A_BYTES); };
    auto sBh = [&](int s) { return (__nv_bfloat16*)(smem_raw + s * STAGE_BYTES + 2 * A_BYTES); };
    auto sBl = [&](int s) { return (__nv_bfloat16*)(smem_raw + s * STAGE_BYTES + 2 * A_BYTES + B_BYTES); };

    auto copy_stage = [&](int s, int kt) {
        const int k0 = kt * 16;
        cp16(smem_u32(sAh(s) + ar * AST + ac), g_Ah + (size_t)(mrow0 + ar) * K + k0 + ac);
        cp16(smem_u32(sAl(s) + ar * AST + ac), g_Al + (size_t)(mrow0 + ar) * K + k0 + ac);
        if (bvalid) {
            cp16(smem_u32(sBh(s) + br * BST + bc), g_Bh + (size_t)(k0 + br) * N + colBase + bc);
            cp16(smem_u32(sBl(s) + br * BST + bc), g_Bl + (size_t)(k0 + br) * N + colBase + bc);
        } else {
            uint4 z = make_uint4(0, 0, 0, 0);
            *(uint4*)(sBh(s) + br * BST + bc) = z;
            *(uint4*)(sBl(s) + br * BST + bc) = z;
        }
    };

    float acc[4][4][4];
#pragma unroll
    for (int mt = 0; mt < 4; mt++)
#pragma unroll
        for (int nt = 0; nt < 4; nt++)
#pragma unroll
            for (int r = 0; r < 4; r++) acc[mt][nt][r] = 0.f;

    const int KT = K / 16;
#pragma unroll
    for (int s = 0; s < STAGES - 1; s++) {
        copy_stage(s, s);
        asm volatile("cp.async.commit_group;\n" ::: "memory");
    }

    const int m8 = lane >> 3;
    const int j8 = lane & 7;

    for (int kt = 0; kt < KT; kt++) {
        asm volatile("cp.async.wait_group %0;\n" :: "n"(STAGES - 2) : "memory");
        __syncthreads();

        const int nk = kt + STAGES - 1;
        if (nk < KT) copy_stage(nk & (STAGES - 1), nk);
        asm volatile("cp.async.commit_group;\n" ::: "memory");

        const int buf = kt & (STAGES - 1);
        const __nv_bfloat16* Ahs = sAh(buf);
        const __nv_bfloat16* Als = sAl(buf);
        const __nv_bfloat16* Bhs = sBh(buf);
        const __nv_bfloat16* Bls = sBl(buf);

        uint32_t ah[4][4], al[4][4], bh[4][2], bl[4][2];
#pragma unroll
        for (int mt = 0; mt < 4; mt++) {
            const int row = wm * 64 + mt * 16 + (m8 & 1) * 8 + j8;
            const int kc  = (m8 >> 1) * 8;
            ldsm_x4(ah[mt][0], ah[mt][1], ah[mt][2], ah[mt][3],
                    smem_u32(Ahs + row * AST + kc));
            ldsm_x4(al[mt][0], al[mt][1], al[mt][2], al[mt][3],
                    smem_u32(Als + row * AST + kc));
        }
#pragma unroll
        for (int nt2 = 0; nt2 < 2; nt2++) {
            const int kk = (m8 & 1) * 8 + j8;
            const int nn = wn * 32 + nt2 * 16 + (m8 >> 1) * 8;
            uint32_t r0, r1, r2, r3;
            ldsm_x4_t(r0, r1, r2, r3, smem_u32(Bhs + kk * BST + nn));
            bh[nt2 * 2][0] = r0; bh[nt2 * 2][1] = r1;
            bh[nt2 * 2 + 1][0] = r2; bh[nt2 * 2 + 1][1] = r3;
            ldsm_x4_t(r0, r1, r2, r3, smem_u32(Bls + kk * BST + nn));
            bl[nt2 * 2][0] = r0; bl[nt2 * 2][1] = r1;
            bl[nt2 * 2 + 1][0] = r2; bl[nt2 * 2 + 1][1] = r3;
        }

#pragma unroll
        for (int mt = 0; mt < 4; mt++)
#pragma unroll
            for (int nt = 0; nt < 4; nt++) {
                mma_bf16(acc[mt][nt], al[mt], bh[nt]);
                mma_bf16(acc[mt][nt], ah[mt], bl[nt]);
                mma_bf16(acc[mt][nt], ah[mt], bh[nt]);
            }
        __syncthreads();
    }

    const int g4 = lane >> 2;
    const int tg = lane & 3;
#pragma unroll
    for (int mt = 0; mt < 4; mt++) {
        const int row0 = mrow0 + wm * 64 + mt * 16 + g4;
        float* C0 = g_proj + (size_t)row0 * N;
        float* C1 = g_proj + (size_t)(row0 + 8) * N;
#pragma unroll
        for (int nt = 0; nt < 4; nt++) {
            const int col = colBase + wn * 32 + nt * 8 + tg * 2;
            if (col < N) {
                *(float2*)(C0 + col) = make_float2(acc[mt][nt][0], acc[mt][nt][1]);
                *(float2*)(C1 + col) = make_float2(acc[mt][nt][2], acc[mt][nt][3]);
            }
        }
    }
}

// ---------------------------------------------------------------------------
// Kernel 2: per-(b,l,h) scalars
// ---------------------------------------------------------------------------
__global__ void scalars_kernel(const float* __restrict__ A_log,
                               const float* __restrict__ dt_bias)
{
    int i = blockIdx.x * blockDim.x + threadIdx.x;
    if (i >= BL * N_HEADS) return;
    int bl = i >> 4;
    int h  = i & 15;
    const float* row = g_proj + (size_t)bl * TOTAL_PROJ;
    float bv = row[12288 + h];
    g_beta[i] = 1.f / (1.f + expf(-bv));
    float a = row[12304 + h] + dt_bias[h];
    float sp = (a > 15.f) ? a : log1pf(expf(a));
    float g = -expf(A_log[h]) * sp;
    g_eg[i] = expf(g);
}

// ---------------------------------------------------------------------------
// Kernel 3: depthwise causal conv(4) + SiLU + per-head L2 norm (q,k only)
// ---------------------------------------------------------------------------
#define CTILE 8
__global__ __launch_bounds__(128) void conv_kernel(const float* __restrict__ Wconv)
{
    const int grp  = blockIdx.x;
    const int tile = blockIdx.y;
    const int b    = tile / (L_SEQ / CTILE);
    const int l0   = (tile % (L_SEQ / CTILE)) * CTILE;
    const int c    = grp * 128 + threadIdx.x;
    const int lane = threadIdx.x & 31;
    const int wid  = threadIdx.x >> 5;

    const float* w = Wconv + c * 4;
    const float w0 = w[0], w1 = w[1], w2 = w[2], w3 = w[3];

    const float* pbase = g_proj + ((size_t)(b * L_SEQ + l0)) * TOTAL_PROJ + c;
    float xv[CTILE + 3];
#pragma unroll
    for (int j = 0; j < CTILE + 3; j++) {
        const int l = l0 - 3 + j;
        xv[j] = (l >= 0) ? pbase[(ptrdiff_t)(j - 3) * TOTAL_PROJ] : 0.f;
    }

    __shared__ float red[4];
    float* yrow = g_y + ((size_t)(b * L_SEQ + l0)) * CONV_CH + c;

#pragma unroll
    for (int t = 0; t < CTILE; t++) {
        float acc = xv[t] * w0 + xv[t + 1] * w1 + xv[t + 2] * w2 + xv[t + 3] * w3;
        float s = acc / (1.f + expf(-acc));
        float val = s;
        if (grp < 32) {
            float ss = s * s;
#pragma unroll
            for (int off = 16; off > 0; off >>= 1)
                ss += __shfl_xor_sync(0xffffffffu, ss, off);
            if (lane == 0) red[wid] = ss;
            __syncthreads();
            float tot = red[0] + red[1] + red[2] + red[3];
            val = s * rsqrtf(tot + 1e-6f);
            __syncthreads();
        }
        yrow[(size_t)t * CONV_CH] = val;
    }
}

// ---------------------------------------------------------------------------
// Kernel 4: gated delta-rule recurrence.
// 3-group x 4-step cp.async ring; ONE wait+barrier per 4 timesteps.
// Grid: 128 CTAs = (b,h) x 4 v-slices of 64 cols. 256 threads:
//   col = tid>>2 (0..63), kp = tid&3; thread owns S rows kp*32..kp*32+31.
// Stage layout (floats), stride 420:
//   k at [(j>>5)*36 + (j&31)], q at [144 + same], v [288..351],
//   gate [352..415], eg [416], beta [417].
// ---------------------------------------------------------------------------
#define RGROUPS 3
#define GSTEPS  4
#define RSTAGES (RGROUPS * GSTEPS)   // 12
#define RSTRIDE 420
#define NGROUPS (L_SEQ / GSTEPS)     // 512

__global__ __launch_bounds__(256, 1) void recurrence_kernel(float* __restrict__ out)
{
    const int slice = blockIdx.x & 3;
    const int bh    = blockIdx.x >> 2;
    const int b     = bh >> 4;
    const int h     = bh & 15;
    const int tid   = threadIdx.x;
    const int col   = tid >> 2;
    const int kp    = tid & 3;
    const int vcol  = slice * 64 + col;

    __shared__ __align__(16) float ring[RSTAGES * RSTRIDE];

    float S[32];
#pragma unroll
    for (int j = 0; j < 32; j++) S[j] = 0.f;

    const float scale = 0.08838834764831845f;   // 128^-0.5

    const size_t ybase = (size_t)b * L_SEQ * CONV_CH;
    const size_t pbase = (size_t)b * L_SEQ * TOTAL_PROJ;
    const int qofs  = h * 128;
    const int kofs  = KEY_DIM + h * 128;
    const int vofs0 = 2 * KEY_DIM + h * 256 + slice * 64;
    const int gofs0 = 2 * KEY_DIM + VALUE_DIM + h * 256 + slice * 64;
    const int ghofs = (b * L_SEQ) * N_HEADS + h;

    const uint32_t ring_u32 = smem_u32(ring);

    auto slot_of = [&](int t) -> int {
        return ((t >> 2) % RGROUPS) * GSTEPS + (t & 3);
    };

    auto issue_stage = [&](int t) {
        const uint32_t sb = ring_u32 + (uint32_t)(slot_of(t) * RSTRIDE * 4);
        const size_t yb = ybase + (size_t)t * CONV_CH;
        if (tid < 32) {
            const int j0 = tid * 4;
            const uint32_t dst = (uint32_t)(((j0 >> 5) * 36 + (j0 & 31)) * 4);
            cp16(sb + dst, g_y + yb + kofs + j0);
        } else if (tid < 64) {
            const int j0 = (tid - 32) * 4;
            const uint32_t dst = (uint32_t)((144 + (j0 >> 5) * 36 + (j0 & 31)) * 4);
            cp16(sb + dst, g_y + yb + qofs + j0);
        } else if (tid < 80) {
            const int i = tid - 64;
            cp16(sb + (uint32_t)((288 + i * 4) * 4), g_y + yb + vofs0 + i * 4);
        } else if (tid < 96) {
            const int i = tid - 80;
            cp16(sb + (uint32_t)((352 + i * 4) * 4),
                 g_proj + pbase + (size_t)t * TOTAL_PROJ + gofs0 + i * 4);
        } else if (tid == 96) {
            cp4(sb + 416 * 4, g_eg + ghofs + t * N_HEADS);
        } else if (tid == 97) {
            cp4(sb + 417 * 4, g_beta + ghofs + t * N_HEADS);
        }
    };

    auto issue_group = [&](int G) {
#pragma unroll
        for (int s = 0; s < GSTEPS; s++) issue_stage(G * GSTEPS + s);
    };

    // prologue: 2 groups in flight
    issue_group(0);
    asm volatile("cp.async.commit_group;\n" ::: "memory");
    issue_group(1);
    asm volatile("cp.async.commit_group;\n" ::: "memory");

    for (int g = 0; g < NGROUPS; g++) {
        asm volatile("cp.async.wait_group 1;\n" ::: "memory");
        __syncthreads();

        // refill slot of group g-1 (fully drained: barrier above covers iter g-1 reads)
        if (g + 2 < NGROUPS) issue_group(g + 2);
        asm volatile("cp.async.commit_group;\n" ::: "memory");

#pragma unroll
        for (int i = 0; i < GSTEPS; i++) {
            const int t = g * GSTEPS + i;
            const float* sb = ring + slot_of(t) * RSTRIDE;
            const float eg   = sb[416];
            const float bt   = sb[417];
            const float vv   = sb[288 + col];
            const float gate = sb[352 + col];
            const float4* k4 = (const float4*)(sb + kp * 36);
            const float4* q4 = (const float4*)(sb + 144 + kp * 36);

            float kreg[32];
            float kv0 = 0.f, kv1 = 0.f, kv2 = 0.f, kv3 = 0.f;
#pragma unroll
            for (int u = 0; u < 8; u++) {
                float4 kv4 = k4[u];
                kreg[u * 4 + 0] = kv4.x; kreg[u * 4 + 1] = kv4.y;
                kreg[u * 4 + 2] = kv4.z; kreg[u * 4 + 3] = kv4.w;
                kv0 += kv4.x * S[u * 4 + 0];
                kv1 += kv4.y * S[u * 4 + 1];
                kv2 += kv4.z * S[u * 4 + 2];
                kv3 += kv4.w * S[u * 4 + 3];
            }
            float kv = (kv0 + kv1) + (kv2 + kv3);
            kv += __shfl_xor_sync(0xffffffffu, kv, 1);
            kv += __shfl_xor_sync(0xffffffffu, kv, 2);

            const float delta = (vv - eg * kv) * bt;

            float qs0 = 0.f, qs1 = 0.f, qs2 = 0.f, qs3 = 0.f;
#pragma unroll
            for (int u = 0; u < 8; u++) {
                float4 qv4 = q4[u];
                float s0 = eg * S[u * 4 + 0] + kreg[u * 4 + 0] * delta;
                float s1 = eg * S[u * 4 + 1] + kreg[u * 4 + 1] * delta;
                float s2 = eg * S[u * 4 + 2] + kreg[u * 4 + 2] * delta;
                float s3 = eg * S[u * 4 + 3] + kreg[u * 4 + 3] * delta;
                S[u * 4 + 0] = s0; S[u * 4 + 1] = s1;
                S[u * 4 + 2] = s2; S[u * 4 + 3] = s3;
                qs0 += qv4.x * s0;
                qs1 += qv4.y * s1;
                qs2 += qv4.z * s2;
                qs3 += qv4.w * s3;
            }
            float qs = (qs0 + qs1) + (qs2 + qs3);
            qs += __shfl_xor_sync(0xffffffffu, qs, 1);
            qs += __shfl_xor_sync(0xffffffffu, qs, 2);

            if (kp == 0) {
                const float o  = qs * scale;
                const float sg = gate / (1.f + expf(-gate));
                out[((size_t)(b * L_SEQ + t) * N_HEADS + h) * HEAD_V + vcol] = o * sg;
            }
        }
    }
}

// ---------------------------------------------------------------------------
// Launch
// ---------------------------------------------------------------------------
extern "C" void kernel_launch(void* const* d_in, const int* in_sizes, int n_in,
                              void* d_out, int out_size)
{
    const float* X       = (const float*)d_in[0];
    const float* W       = (const float*)d_in[1];
    const float* Wconv   = (const float*)d_in[2];
    const float* A_log   = (const float*)d_in[3];
    const float* dt_bias = (const float*)d_in[4];
    float* out = (float*)d_out;

    cudaFuncSetAttribute(mma_gemm_kernel,
                         cudaFuncAttributeMaxDynamicSharedMemorySize,
                         SMEM_TOTAL_GEMM);

    split_kernel<<<2048, 256>>>(X, W);

    dim3 gemmGrid(BL / 128, (TOTAL_PROJ + 127) / 128);
    mma_gemm_kernel<<<gemmGrid, 256, SMEM_TOTAL_GEMM>>>();

    scalars_kernel<<<(BL * N_HEADS + 255) / 256, 256>>>(A_log, dt_bias);

    dim3 convGrid(CONV_CH / 128, BL / CTILE);
    conv_kernel<<<convGrid, 128>>>(Wconv);

    recurrence_kernel<<<B_SZ * N_HEADS * 4, 256>>>(out);
}